// round 6
// baseline (speedup 1.0000x reference)
#include <cuda_runtime.h>
#include <cuda_bf16.h>
#include <math.h>
#include <stdint.h>

#define NB 4
#define SEQL 2048
#define DMODEL 512
#define NHEAD 8
#define HDIM 64
#define WINDOW 256
#define MTOT (NB*SEQL)
#define XSZ ((size_t)MTOT*DMODEL)
#define WSZ ((size_t)DMODEL*DMODEL)

__device__ __align__(16) float g_pre[MTOT*DMODEL];
__device__ __align__(16) __nv_bfloat16 g_Wh[4*DMODEL*DMODEL];
__device__ __align__(16) __nv_bfloat16 g_Wl[4*DMODEL*DMODEL];
__device__ __align__(16) __nv_bfloat16 g_Xh[3*MTOT*DMODEL];
__device__ __align__(16) __nv_bfloat16 g_Xl[3*MTOT*DMODEL];
__device__ __align__(16) __nv_bfloat16 g_QKVh[3*MTOT*DMODEL];
__device__ __align__(16) __nv_bfloat16 g_QKVl[3*MTOT*DMODEL];
__device__ __align__(16) __nv_bfloat16 g_Ch[MTOT*DMODEL];
__device__ __align__(16) __nv_bfloat16 g_Cl[MTOT*DMODEL];

__device__ __forceinline__ uint32_t smem_u32(const void* p) {
    uint32_t a;
    asm("{ .reg .u64 t; cvta.to.shared.u64 t, %1; cvt.u32.u64 %0, t; }" : "=r"(a) : "l"(p));
    return a;
}
__device__ __forceinline__ void cpa16(uint32_t dst, const void* src) {
    asm volatile("cp.async.cg.shared.global [%0], [%1], 16;" :: "r"(dst), "l"(src));
}
#define CP_COMMIT() asm volatile("cp.async.commit_group;")
#define CP_WAIT(n)  asm volatile("cp.async.wait_group " #n ";")
__device__ __forceinline__ void ldmx4(uint32_t a, uint32_t* r) {
    asm volatile("ldmatrix.sync.aligned.m8n8.x4.shared.b16 {%0,%1,%2,%3}, [%4];"
                 : "=r"(r[0]), "=r"(r[1]), "=r"(r[2]), "=r"(r[3]) : "r"(a));
}
__device__ __forceinline__ void ldmx4t(uint32_t a, uint32_t* r) {
    asm volatile("ldmatrix.sync.aligned.m8n8.x4.trans.shared.b16 {%0,%1,%2,%3}, [%4];"
                 : "=r"(r[0]), "=r"(r[1]), "=r"(r[2]), "=r"(r[3]) : "r"(a));
}
__device__ __forceinline__ void mma16816(float* d, const uint32_t* a, const uint32_t* b) {
    asm volatile("mma.sync.aligned.m16n8k16.row.col.f32.bf16.bf16.f32 "
                 "{%0,%1,%2,%3}, {%4,%5,%6,%7}, {%8,%9}, {%0,%1,%2,%3};"
                 : "+f"(d[0]), "+f"(d[1]), "+f"(d[2]), "+f"(d[3])
                 : "r"(a[0]), "r"(a[1]), "r"(a[2]), "r"(a[3]), "r"(b[0]), "r"(b[1]));
}
__device__ __forceinline__ uint32_t packbf(float v0, float v1) {
    uint32_t r;
    asm("cvt.rn.bf16x2.f32 %0, %1, %2;" : "=r"(r) : "f"(v1), "f"(v0));
    return r;
}
__device__ __forceinline__ void split2(float v0, float v1, uint32_t& h, uint32_t& l) {
    h = packbf(v0, v1);
    l = packbf(v0 - __uint_as_float(h << 16), v1 - __uint_as_float(h & 0xFFFF0000u));
}

// ---- prep: W^T hi/lo (0.125 folded into W_Q) --------------------------------
__global__ __launch_bounds__(256)
void prep_w_kernel(const float* __restrict__ w0, const float* __restrict__ w1,
                   const float* __restrict__ w2, const float* __restrict__ w3)
{
    __shared__ float s[32][33];
    const int wsel = blockIdx.z;
    const float* W = (wsel == 0) ? w0 : (wsel == 1) ? w1 : (wsel == 2) ? w2 : w3;
    const float scale = (wsel == 0) ? 0.125f : 1.0f;
    const int k0 = blockIdx.x * 32, n0 = blockIdx.y * 32;
    const int tx = threadIdx.x, ty = threadIdx.y;
    #pragma unroll
    for (int i = 0; i < 4; i++)
        s[ty + 8 * i][tx] = W[(size_t)(k0 + ty + 8 * i) * DMODEL + n0 + tx];
    __syncthreads();
    const size_t base = (size_t)wsel * WSZ;
    #pragma unroll
    for (int i = 0; i < 4; i++) {
        int n = n0 + ty + 8 * i, k = k0 + tx;
        float x = s[tx][ty + 8 * i] * scale;
        __nv_bfloat16 h = __float2bfloat16(x);
        g_Wh[base + (size_t)n * DMODEL + k] = h;
        g_Wl[base + (size_t)n * DMODEL + k] = __float2bfloat16(x - __bfloat162float(h));
    }
}

// ---- prep: inputs fp32 -> bf16 hi/lo -----------------------------------------
__global__ __launch_bounds__(256)
void prep_x_kernel(const float* __restrict__ x0, const float* __restrict__ x1,
                   const float* __restrict__ x2)
{
    const int sel = blockIdx.y;
    const float* x = (sel == 0) ? x0 : (sel == 1) ? x1 : x2;
    size_t i4 = (size_t)blockIdx.x * 256 + threadIdx.x;
    float4 v = ((const float4*)x)[i4];
    uint32_t h0, l0, h1, l1;
    split2(v.x, v.y, h0, l0);
    split2(v.z, v.w, h1, l1);
    const size_t base = (size_t)sel * XSZ;
    ((uint2*)(g_Xh + base))[i4] = make_uint2(h0, h1);
    ((uint2*)(g_Xl + base))[i4] = make_uint2(l0, l1);
}

// ---- tensor-core GEMM: BK=32, hi/lo fused rows, 3-stage, 2 CTAs/SM -----------
// stage (32KB): A rows 0-127 @0 (128B row: chunks 0-3 hi, 4-7 lo), B @16384.
#define STG32 32768
__device__ __forceinline__ void stage32(uint32_t sbase,
    const __nv_bfloat16* __restrict__ Ah, const __nv_bfloat16* __restrict__ Al,
    const __nv_bfloat16* __restrict__ Bh, const __nv_bfloat16* __restrict__ Bl,
    int arow, int brow, int k0, int tid)
{
    #pragma unroll
    for (int i = 0; i < 8; i++) {
        int idx = tid + i * 256;
        int isB = idx >> 10, rem = idx & 1023;
        int r = rem >> 3, c = rem & 7;
        const __nv_bfloat16* src = isB ? ((c < 4) ? Bh : Bl) : ((c < 4) ? Ah : Al);
        int row = (isB ? brow : arow) + r;
        cpa16(sbase + (uint32_t)(isB << 14) + (uint32_t)r * 128u
                    + (uint32_t)((c ^ (r & 7)) << 4),
              src + (size_t)row * DMODEL + k0 + (c & 3) * 8);
    }
}

template<int MODE>
__global__ __launch_bounds__(256, 2)
void gemm_tc(const __nv_bfloat16* __restrict__ Ah_, const __nv_bfloat16* __restrict__ Al_,
             const __nv_bfloat16* __restrict__ Wh_, const __nv_bfloat16* __restrict__ Wl_,
             const float* __restrict__ resid, float* __restrict__ outF,
             __nv_bfloat16* __restrict__ outH, __nv_bfloat16* __restrict__ outL)
{
    extern __shared__ char dyn[];
    const uint32_t sb = smem_u32(dyn);
    const int tid = threadIdx.x, wid = tid >> 5, lane = tid & 31;
    const int wm = wid & 1, wn = wid >> 1;
    const int g8 = lane >> 3, r8 = lane & 7;
    const int bx = blockIdx.x, by = blockIdx.y;
    const int wsel = (MODE == 0) ? (int)blockIdx.z : 0;
    const __nv_bfloat16* Ah = Ah_ + (size_t)wsel * XSZ;
    const __nv_bfloat16* Al = Al_ + (size_t)wsel * XSZ;
    const __nv_bfloat16* Bh = Wh_ + (size_t)wsel * WSZ;
    const __nv_bfloat16* Bl = Wl_ + (size_t)wsel * WSZ;
    const int arow = by * 128, brow = bx * 128;

    float d[4][4][4];
    #pragma unroll
    for (int mi = 0; mi < 4; mi++)
        #pragma unroll
        for (int ni = 0; ni < 4; ni++)
            #pragma unroll
            for (int q = 0; q < 4; q++) d[mi][ni][q] = 0.0f;

    stage32(sb,         Ah, Al, Bh, Bl, arow, brow, 0,  tid); CP_COMMIT();
    stage32(sb + STG32, Ah, Al, Bh, Bl, arow, brow, 32, tid); CP_COMMIT();

    for (int c = 0; c < 16; c++) {
        if (c + 2 < 16) {
            stage32(sb + (uint32_t)((c + 2) % 3) * STG32,
                    Ah, Al, Bh, Bl, arow, brow, (c + 2) * 32, tid);
            CP_COMMIT(); CP_WAIT(2);
        } else if (c + 1 < 16) { CP_WAIT(1); }
        else { CP_WAIT(0); }
        __syncthreads();

        const uint32_t ss = sb + (uint32_t)(c % 3) * STG32;
        #pragma unroll
        for (int k16 = 0; k16 < 2; k16++) {
            uint32_t ah[4][4], al[4][4], bh[8], bl[8];
            #pragma unroll
            for (int mi = 0; mi < 4; mi++) {
                int row = wm * 64 + mi * 16 + r8 + (g8 & 1) * 8;
                int ch  = k16 * 2 + (g8 >> 1);
                uint32_t base = ss + (uint32_t)row * 128u;
                ldmx4(base + (uint32_t)((ch       ^ (row & 7)) << 4), ah[mi]);
                ldmx4(base + (uint32_t)(((ch + 4) ^ (row & 7)) << 4), al[mi]);
            }
            #pragma unroll
            for (int np = 0; np < 2; np++) {
                int row = wn * 32 + np * 16 + r8 + (g8 >> 1) * 8;
                int ch  = k16 * 2 + (g8 & 1);
                uint32_t base = ss + 16384u + (uint32_t)row * 128u;
                ldmx4(base + (uint32_t)((ch       ^ (row & 7)) << 4), &bh[np * 4]);
                ldmx4(base + (uint32_t)(((ch + 4) ^ (row & 7)) << 4), &bl[np * 4]);
            }
            #pragma unroll
            for (int mi = 0; mi < 4; mi++)
                #pragma unroll
                for (int ni = 0; ni < 4; ni++) {
                    mma16816(d[mi][ni], ah[mi], &bh[ni * 2]);
                    mma16816(d[mi][ni], al[mi], &bh[ni * 2]);
                    mma16816(d[mi][ni], ah[mi], &bl[ni * 2]);
                }
        }
        __syncthreads();
    }

    const int rbase = by * 128 + wm * 64 + (lane >> 2);
    const int cbase = bx * 128 + wn * 32 + (lane & 3) * 2;
    #pragma unroll
    for (int mi = 0; mi < 4; mi++)
        #pragma unroll
        for (int ni = 0; ni < 4; ni++) {
            int col = cbase + ni * 8;
            #pragma unroll
            for (int hf = 0; hf < 2; hf++) {
                int row = rbase + mi * 16 + hf * 8;
                size_t off = (size_t)row * DMODEL + col;
                if (MODE == 0) {
                    uint32_t hh, ll;
                    split2(d[mi][ni][hf * 2], d[mi][ni][hf * 2 + 1], hh, ll);
                    *(uint32_t*)(outH + (size_t)wsel * XSZ + off) = hh;
                    *(uint32_t*)(outL + (size_t)wsel * XSZ + off) = ll;
                } else {
                    float2 rv = *(const float2*)(resid + off);
                    *(float2*)(outF + off) = make_float2(d[mi][ni][hf * 2] + rv.x,
                                                         d[mi][ni][hf * 2 + 1] + rv.y);
                }
            }
        }
}

// ---- tensor-core banded flash attention (unchanged from R5) -------------------
__device__ __forceinline__ void stage_kv(uint32_t sb, int s, int b, int h,
                                         int krow0, int tid)
{
    const uint32_t base = sb + 16384u + (uint32_t)s * 32768u;
    #pragma unroll
    for (int i = 0; i < 16; i++) {
        int idx = tid + i * 128;
        int mat = idx >> 9, rem = idx & 511;
        int r = rem >> 3, ch = rem & 7;
        const __nv_bfloat16* src =
            (mat == 0 ? g_QKVh + 1 * XSZ : mat == 1 ? g_QKVl + 1 * XSZ :
             mat == 2 ? g_QKVh + 2 * XSZ : g_QKVl + 2 * XSZ)
            + (size_t)(b * SEQL + krow0 + r) * DMODEL + h * HDIM + ch * 8;
        cpa16(base + (uint32_t)mat * 8192u + (uint32_t)r * 128u
                   + (uint32_t)((ch ^ (r & 7)) << 4), src);
    }
}

__global__ __launch_bounds__(128, 2)
void attn_tc()
{
    extern __shared__ char dyn[];
    const uint32_t sb = smem_u32(dyn);
    const int tid = threadIdx.x, wid = tid >> 5, lane = tid & 31;
    const int r8 = lane & 7, g8 = lane >> 3;
    const int qt = blockIdx.x, h = blockIdx.y, b = blockIdx.z;
    const int q0 = qt * 64;

    #pragma unroll
    for (int i = 0; i < 8; i++) {
        int idx = tid + i * 128;
        int mat = idx >> 9, rem = idx & 511;
        int r = rem >> 3, ch = rem & 7;
        const __nv_bfloat16* src = (mat ? g_QKVl : g_QKVh)
            + (size_t)(b * SEQL + q0 + r) * DMODEL + h * HDIM + ch * 8;
        cpa16(sb + (uint32_t)mat * 8192u + (uint32_t)r * 128u
                 + (uint32_t)((ch ^ (r & 7)) << 4), src);
    }
    const int kt_lo = (qt >= 4) ? qt - 4 : 0;
    stage_kv(sb, 0, b, h, kt_lo * 64, tid);
    CP_COMMIT(); CP_WAIT(0);
    __syncthreads();

    uint32_t qh[4][4], ql[4][4];
    #pragma unroll
    for (int k16 = 0; k16 < 4; k16++) {
        int row = wid * 16 + r8 + (g8 & 1) * 8;
        int ch  = k16 * 2 + (g8 >> 1);
        uint32_t off = (uint32_t)row * 128u + (uint32_t)((ch ^ (row & 7)) << 4);
        ldmx4(sb + off, qh[k16]);
        ldmx4(sb + 8192u + off, ql[k16]);
    }

    float o[8][4];
    #pragma unroll
    for (int ni = 0; ni < 8; ni++)
        #pragma unroll
        for (int c = 0; c < 4; c++) o[ni][c] = 0.0f;
    float m_run[2] = {-1e30f, -1e30f}, l_run[2] = {0.0f, 0.0f};

    for (int kt = kt_lo; kt <= qt; kt++) {
        const int s = (kt - kt_lo) & 1;
        if (kt < qt) { stage_kv(sb, s ^ 1, b, h, (kt + 1) * 64, tid); CP_COMMIT(); }
        const uint32_t kb = sb + 16384u + (uint32_t)s * 32768u;

        float sc[8][4];
        #pragma unroll
        for (int ni = 0; ni < 8; ni++)
            #pragma unroll
            for (int c = 0; c < 4; c++) sc[ni][c] = 0.0f;

        #pragma unroll
        for (int k16 = 0; k16 < 4; k16++) {
            uint32_t kh[4][4], kl[4][4];
            #pragma unroll
            for (int ng = 0; ng < 4; ng++) {
                int row = ng * 16 + r8 + (g8 >> 1) * 8;
                int ch  = k16 * 2 + (g8 & 1);
                uint32_t off = (uint32_t)row * 128u + (uint32_t)((ch ^ (row & 7)) << 4);
                ldmx4(kb + off, kh[ng]);
                ldmx4(kb + 8192u + off, kl[ng]);
            }
            #pragma unroll
            for (int ng = 0; ng < 4; ng++)
                #pragma unroll
                for (int hf = 0; hf < 2; hf++) {
                    int ni = ng * 2 + hf;
                    mma16816(sc[ni], qh[k16], &kh[ng][hf * 2]);
                    mma16816(sc[ni], ql[k16], &kh[ng][hf * 2]);
                    mma16816(sc[ni], qh[k16], &kl[ng][hf * 2]);
                }
        }

        const int k0 = kt * 64;
        if (kt == qt || (qt >= 4 && kt == qt - 4)) {
            const bool diag = (kt == qt);
            const int qr0 = q0 + wid * 16 + (lane >> 2);
            #pragma unroll
            for (int ni = 0; ni < 8; ni++) {
                int kj = k0 + ni * 8 + 2 * (lane & 3);
                #pragma unroll
                for (int c = 0; c < 4; c++) {
                    int kcol = kj + (c & 1), qrow = qr0 + (c >> 1) * 8;
                    bool ok = diag ? (kcol <= qrow) : (kcol >= qrow - (WINDOW - 1));
                    if (!ok) sc[ni][c] = -INFINITY;
                }
            }
        }

        float mt0 = -INFINITY, mt1 = -INFINITY;
        #pragma unroll
        for (int ni = 0; ni < 8; ni++) {
            mt0 = fmaxf(mt0, fmaxf(sc[ni][0], sc[ni][1]));
            mt1 = fmaxf(mt1, fmaxf(sc[ni][2], sc[ni][3]));
        }
        #pragma unroll
        for (int off = 1; off <= 2; off <<= 1) {
            mt0 = fmaxf(mt0, __shfl_xor_sync(0xffffffffu, mt0, off));
            mt1 = fmaxf(mt1, __shfl_xor_sync(0xffffffffu, mt1, off));
        }
        float mn0 = fmaxf(m_run[0], mt0), mn1 = fmaxf(m_run[1], mt1);
        float e0 = __expf(m_run[0] - mn0), e1 = __expf(m_run[1] - mn1);
        float sum0 = 0.0f, sum1 = 0.0f;
        #pragma unroll
        for (int ni = 0; ni < 8; ni++) {
            sc[ni][0] = __expf(sc[ni][0] - mn0); sum0 += sc[ni][0];
            sc[ni][1] = __expf(sc[ni][1] - mn0); sum0 += sc[ni][1];
            sc[ni][2] = __expf(sc[ni][2] - mn1); sum1 += sc[ni][2];
            sc[ni][3] = __expf(sc[ni][3] - mn1); sum1 += sc[ni][3];
        }
        #pragma unroll
        for (int off = 1; off <= 2; off <<= 1) {
            sum0 += __shfl_xor_sync(0xffffffffu, sum0, off);
            sum1 += __shfl_xor_sync(0xffffffffu, sum1, off);
        }
        l_run[0] = l_run[0] * e0 + sum0;
        l_run[1] = l_run[1] * e1 + sum1;
        m_run[0] = mn0; m_run[1] = mn1;
        #pragma unroll
        for (int ni = 0; ni < 8; ni++) {
            o[ni][0] *= e0; o[ni][1] *= e0; o[ni][2] *= e1; o[ni][3] *= e1;
        }

        uint32_t ph[4][4], pl[4][4];
        #pragma unroll
        for (int t = 0; t < 4; t++) {
            split2(sc[2*t][0],   sc[2*t][1],   ph[t][0], pl[t][0]);
            split2(sc[2*t][2],   sc[2*t][3],   ph[t][1], pl[t][1]);
            split2(sc[2*t+1][0], sc[2*t+1][1], ph[t][2], pl[t][2]);
            split2(sc[2*t+1][2], sc[2*t+1][3], ph[t][3], pl[t][3]);
        }

        const uint32_t vb = kb + 16384u;
        #pragma unroll
        for (int kt16 = 0; kt16 < 4; kt16++) {
            uint32_t vh[4][4], vl[4][4];
            #pragma unroll
            for (int ng = 0; ng < 4; ng++) {
                int row = kt16 * 16 + r8 + (g8 & 1) * 8;
                int ch  = ng * 2 + (g8 >> 1);
                uint32_t off = (uint32_t)row * 128u + (uint32_t)((ch ^ (row & 7)) << 4);
                ldmx4t(vb + off, vh[ng]);
                ldmx4t(vb + 8192u + off, vl[ng]);
            }
            #pragma unroll
            for (int ng = 0; ng < 4; ng++)
                #pragma unroll
                for (int hf = 0; hf < 2; hf++) {
                    int ni = ng * 2 + hf;
                    mma16816(o[ni], ph[kt16], &vh[ng][hf * 2]);
                    mma16816(o[ni], pl[kt16], &vh[ng][hf * 2]);
                    mma16816(o[ni], ph[kt16], &vl[ng][hf * 2]);
                }
        }
        if (kt < qt) { CP_WAIT(0); __syncthreads(); }
    }

    const float i0 = 1.0f / l_run[0], i1 = 1.0f / l_run[1];
    const int row0 = q0 + wid * 16 + (lane >> 2);
    #pragma unroll
    for (int ni = 0; ni < 8; ni++) {
        int col = h * HDIM + ni * 8 + 2 * (lane & 3);
        size_t o0 = (size_t)(b * SEQL + row0) * DMODEL + col;
        size_t o1 = o0 + 8 * DMODEL;
        uint32_t hh, ll;
        split2(o[ni][0] * i0, o[ni][1] * i0, hh, ll);
        *(uint32_t*)(g_Ch + o0) = hh; *(uint32_t*)(g_Cl + o0) = ll;
        split2(o[ni][2] * i1, o[ni][3] * i1, hh, ll);
        *(uint32_t*)(g_Ch + o1) = hh; *(uint32_t*)(g_Cl + o1) = ll;
    }
}

// ---- LayerNorm -----------------------------------------------------------------
__global__ __launch_bounds__(256)
void ln_kernel(const float* __restrict__ pre, float* __restrict__ out)
{
    __shared__ float red[16];
    const int row = blockIdx.x, tid = threadIdx.x;
    const float* x = pre + (size_t)row * DMODEL;
    float v0 = x[tid], v1 = x[tid + 256];
    float s = v0 + v1, sq = v0 * v0 + v1 * v1;
    #pragma unroll
    for (int off = 16; off > 0; off >>= 1) {
        s  += __shfl_xor_sync(0xffffffffu, s, off);
        sq += __shfl_xor_sync(0xffffffffu, sq, off);
    }
    if ((tid & 31) == 0) { red[tid >> 5] = s; red[8 + (tid >> 5)] = sq; }
    __syncthreads();
    float st = 0.0f, sqt = 0.0f;
    #pragma unroll
    for (int w = 0; w < 8; w++) { st += red[w]; sqt += red[8 + w]; }
    float mean = st * (1.0f / DMODEL);
    float var  = sqt * (1.0f / DMODEL) - mean * mean;
    float rstd = rsqrtf(var + 1e-5f);
    out[(size_t)row * DMODEL + tid]       = (v0 - mean) * rstd;
    out[(size_t)row * DMODEL + tid + 256] = (v1 - mean) * rstd;
}

// ----------------------------------------------------------------------------------
extern "C" void kernel_launch(void* const* d_in, const int* in_sizes, int n_in,
                              void* d_out, int out_size)
{
    const float* iQ = (const float*)d_in[0];
    const float* iK = (const float*)d_in[1];
    const float* iV = (const float*)d_in[2];
    const float* wQ = (const float*)d_in[3];
    const float* wK = (const float*)d_in[4];
    const float* wV = (const float*)d_in[5];
    const float* wF = (const float*)d_in[6];
    float* out = (float*)d_out;

    float* pPre;
    __nv_bfloat16 *pWh, *pWl, *pXh, *pXl, *pQKVh, *pQKVl, *pCh, *pCl;
    cudaGetSymbolAddress((void**)&pPre,  g_pre);
    cudaGetSymbolAddress((void**)&pWh,   g_Wh);
    cudaGetSymbolAddress((void**)&pWl,   g_Wl);
    cudaGetSymbolAddress((void**)&pXh,   g_Xh);
    cudaGetSymbolAddress((void**)&pXl,   g_Xl);
    cudaGetSymbolAddress((void**)&pQKVh, g_QKVh);
    cudaGetSymbolAddress((void**)&pQKVl, g_QKVl);
    cudaGetSymbolAddress((void**)&pCh,   g_Ch);
    cudaGetSymbolAddress((void**)&pCl,   g_Cl);

    prep_w_kernel<<<dim3(16, 16, 4), dim3(32, 8)>>>(wQ, wK, wV, wF);
    prep_x_kernel<<<dim3(MTOT * DMODEL / 4 / 256, 3), 256>>>(iQ, iK, iV);

    const int gemm_smem = 3 * STG32;   // 98304
    cudaFuncSetAttribute((const void*)gemm_tc<0>,
                         cudaFuncAttributeMaxDynamicSharedMemorySize, gemm_smem);
    cudaFuncSetAttribute((const void*)gemm_tc<1>,
                         cudaFuncAttributeMaxDynamicSharedMemorySize, gemm_smem);
    cudaFuncSetAttribute((const void*)attn_tc,
                         cudaFuncAttributeMaxDynamicSharedMemorySize, 81920);

    gemm_tc<0><<<dim3(4, 64, 3), 256, gemm_smem>>>(pXh, pXl, pWh, pWl,
                                                   nullptr, nullptr, pQKVh, pQKVl);
    attn_tc<<<dim3(SEQL / 64, NHEAD, NB), 128, 81920>>>();
    gemm_tc<1><<<dim3(4, 64), 256, gemm_smem>>>(pCh, pCl, pWh + 3 * WSZ, pWl + 3 * WSZ,
                                                iQ, pPre, nullptr, nullptr);
    ln_kernel<<<MTOT, 256>>>(pPre, out);
}

// round 7
// speedup vs baseline: 1.4455x; 1.4455x over previous
#include <cuda_runtime.h>
#include <cuda_fp16.h>
#include <math.h>
#include <stdint.h>

#define NB 4
#define SEQL 2048
#define DMODEL 512
#define NHEAD 8
#define HDIM 64
#define WINDOW 256
#define MTOT (NB*SEQL)
#define XSZ ((size_t)MTOT*DMODEL)
#define WSZ ((size_t)DMODEL*DMODEL)

__device__ __align__(16) float  g_pre[MTOT*DMODEL];
__device__ __align__(16) __half g_W16[4*DMODEL*DMODEL];   // W^T fp16, [w][n][k]
__device__ __align__(16) __half g_Xh[3*MTOT*DMODEL];      // inputs hi
__device__ __align__(16) __half g_Xl[3*MTOT*DMODEL];      // inputs lo
__device__ __align__(16) __half g_Qh[MTOT*DMODEL];
__device__ __align__(16) __half g_Ql[MTOT*DMODEL];
__device__ __align__(16) __half g_K16[MTOT*DMODEL];
__device__ __align__(16) __half g_V16[MTOT*DMODEL];
__device__ __align__(16) __half g_Ch[MTOT*DMODEL];
__device__ __align__(16) __half g_Cl[MTOT*DMODEL];

__device__ __forceinline__ uint32_t smem_u32(const void* p) {
    uint32_t a;
    asm("{ .reg .u64 t; cvta.to.shared.u64 t, %1; cvt.u32.u64 %0, t; }" : "=r"(a) : "l"(p));
    return a;
}
__device__ __forceinline__ void cpa16(uint32_t dst, const void* src) {
    asm volatile("cp.async.cg.shared.global [%0], [%1], 16;" :: "r"(dst), "l"(src));
}
#define CP_COMMIT() asm volatile("cp.async.commit_group;")
#define CP_WAIT(n)  asm volatile("cp.async.wait_group " #n ";")
__device__ __forceinline__ void ldmx4(uint32_t a, uint32_t* r) {
    asm volatile("ldmatrix.sync.aligned.m8n8.x4.shared.b16 {%0,%1,%2,%3}, [%4];"
                 : "=r"(r[0]), "=r"(r[1]), "=r"(r[2]), "=r"(r[3]) : "r"(a));
}
__device__ __forceinline__ void ldmx4t(uint32_t a, uint32_t* r) {
    asm volatile("ldmatrix.sync.aligned.m8n8.x4.trans.shared.b16 {%0,%1,%2,%3}, [%4];"
                 : "=r"(r[0]), "=r"(r[1]), "=r"(r[2]), "=r"(r[3]) : "r"(a));
}
__device__ __forceinline__ void mma16816(float* d, const uint32_t* a, const uint32_t* b) {
    asm volatile("mma.sync.aligned.m16n8k16.row.col.f32.f16.f16.f32 "
                 "{%0,%1,%2,%3}, {%4,%5,%6,%7}, {%8,%9}, {%0,%1,%2,%3};"
                 : "+f"(d[0]), "+f"(d[1]), "+f"(d[2]), "+f"(d[3])
                 : "r"(a[0]), "r"(a[1]), "r"(a[2]), "r"(a[3]), "r"(b[0]), "r"(b[1]));
}
__device__ __forceinline__ uint32_t packhf(float v0, float v1) {
    __half2 h = __floats2half2_rn(v0, v1);
    return *(uint32_t*)&h;
}
__device__ __forceinline__ void split2h(float v0, float v1, uint32_t& h, uint32_t& l) {
    __half a = __float2half_rn(v0), b = __float2half_rn(v1);
    __half2 hh = __halves2half2(a, b);
    h = *(uint32_t*)&hh;
    l = packhf(v0 - __half2float(a), v1 - __half2float(b));
}

// ---- prep: W^T fp16 (0.125 folded into W_Q) ----------------------------------
__global__ __launch_bounds__(256)
void prep_w_kernel(const float* __restrict__ w0, const float* __restrict__ w1,
                   const float* __restrict__ w2, const float* __restrict__ w3)
{
    __shared__ float s[32][33];
    const int wsel = blockIdx.z;
    const float* W = (wsel == 0) ? w0 : (wsel == 1) ? w1 : (wsel == 2) ? w2 : w3;
    const float scale = (wsel == 0) ? 0.125f : 1.0f;
    const int k0 = blockIdx.x * 32, n0 = blockIdx.y * 32;
    const int tx = threadIdx.x, ty = threadIdx.y;
    #pragma unroll
    for (int i = 0; i < 4; i++)
        s[ty + 8 * i][tx] = W[(size_t)(k0 + ty + 8 * i) * DMODEL + n0 + tx];
    __syncthreads();
    const size_t base = (size_t)wsel * WSZ;
    #pragma unroll
    for (int i = 0; i < 4; i++) {
        int n = n0 + ty + 8 * i, k = k0 + tx;
        g_W16[base + (size_t)n * DMODEL + k] = __float2half_rn(s[tx][ty + 8 * i] * scale);
    }
}

// ---- prep: inputs fp32 -> fp16 hi/lo ------------------------------------------
__global__ __launch_bounds__(256)
void prep_x_kernel(const float* __restrict__ x0, const float* __restrict__ x1,
                   const float* __restrict__ x2)
{
    const int sel = blockIdx.y;
    const float* x = (sel == 0) ? x0 : (sel == 1) ? x1 : x2;
    size_t i4 = (size_t)blockIdx.x * 256 + threadIdx.x;
    float4 v = ((const float4*)x)[i4];
    uint32_t h0, l0, h1, l1;
    split2h(v.x, v.y, h0, l0);
    split2h(v.z, v.w, h1, l1);
    const size_t base = (size_t)sel * XSZ;
    ((uint2*)(g_Xh + base))[i4] = make_uint2(h0, h1);
    ((uint2*)(g_Xl + base))[i4] = make_uint2(l0, l1);
}

// ---- GEMM: fp16 2-term, BK=64, 2-stage, 48KB/stage ----------------------------
// stage: Ah @0, Al @16384, B @32768  (each 128 rows x 128B, XOR-swizzled)
#define STGB 49152
__device__ __forceinline__ void stageABh(uint32_t sbase,
    const __half* __restrict__ Ah, const __half* __restrict__ Al,
    const __half* __restrict__ B, int arow, int brow, int k0, int tid)
{
    #pragma unroll
    for (int i = 0; i < 12; i++) {
        int idx = tid + i * 256;
        int mat = idx >> 10, rem = idx & 1023;
        int r = rem >> 3, c = rem & 7;
        const __half* src = (mat == 0) ? Ah : (mat == 1) ? Al : B;
        int row = ((mat == 2) ? brow : arow) + r;
        cpa16(sbase + (uint32_t)mat * 16384u + (uint32_t)r * 128u
                    + (uint32_t)((c ^ (r & 7)) << 4),
              src + (size_t)row * DMODEL + k0 + c * 8);
    }
}

template<int MODE>
__global__ __launch_bounds__(256)
void gemm_tc(const float* __restrict__ resid, float* __restrict__ outF)
{
    extern __shared__ char dyn[];
    const uint32_t sb = smem_u32(dyn);
    const int tid = threadIdx.x, wid = tid >> 5, lane = tid & 31;
    const int wm = wid & 1, wn = wid >> 1;
    const int g8 = lane >> 3, r8 = lane & 7;
    const int bx = blockIdx.x, by = blockIdx.y;
    const int wsel = (MODE == 0) ? (int)blockIdx.z : 3;
    const __half* Ah = (MODE == 0) ? g_Xh + (size_t)wsel * XSZ : g_Ch;
    const __half* Al = (MODE == 0) ? g_Xl + (size_t)wsel * XSZ : g_Cl;
    const __half* B  = g_W16 + (size_t)wsel * WSZ;
    const int arow = by * 128, brow = bx * 128;

    float d[4][4][4];
    #pragma unroll
    for (int mi = 0; mi < 4; mi++)
        #pragma unroll
        for (int ni = 0; ni < 4; ni++)
            #pragma unroll
            for (int q = 0; q < 4; q++) d[mi][ni][q] = 0.0f;

    stageABh(sb, Ah, Al, B, arow, brow, 0, tid);
    CP_COMMIT();

    for (int c = 0; c < 8; c++) {
        if (c < 7) {
            stageABh(sb + (uint32_t)((c + 1) & 1) * STGB, Ah, Al, B,
                     arow, brow, (c + 1) * 64, tid);
            CP_COMMIT(); CP_WAIT(1);
        } else { CP_WAIT(0); }
        __syncthreads();

        const uint32_t ss = sb + (uint32_t)(c & 1) * STGB;
        #pragma unroll
        for (int k16 = 0; k16 < 4; k16++) {
            uint32_t ah[4][4], al[4][4], bh[8];
            #pragma unroll
            for (int mi = 0; mi < 4; mi++) {
                int row = wm * 64 + mi * 16 + r8 + (g8 & 1) * 8;
                int ch  = k16 * 2 + (g8 >> 1);
                uint32_t off = (uint32_t)row * 128u + (uint32_t)((ch ^ (row & 7)) << 4);
                ldmx4(ss + off, ah[mi]);
                ldmx4(ss + 16384u + off, al[mi]);
            }
            #pragma unroll
            for (int np = 0; np < 2; np++) {
                int row = wn * 32 + np * 16 + r8 + (g8 >> 1) * 8;
                int ch  = k16 * 2 + (g8 & 1);
                uint32_t off = (uint32_t)row * 128u + (uint32_t)((ch ^ (row & 7)) << 4);
                ldmx4(ss + 32768u + off, &bh[np * 4]);
            }
            #pragma unroll
            for (int mi = 0; mi < 4; mi++)
                #pragma unroll
                for (int ni = 0; ni < 4; ni++) {
                    mma16816(d[mi][ni], ah[mi], &bh[ni * 2]);
                    mma16816(d[mi][ni], al[mi], &bh[ni * 2]);
                }
        }
        __syncthreads();
    }

    const int rbase = by * 128 + wm * 64 + (lane >> 2);
    const int cbase = bx * 128 + wn * 32 + (lane & 3) * 2;
    #pragma unroll
    for (int mi = 0; mi < 4; mi++)
        #pragma unroll
        for (int ni = 0; ni < 4; ni++) {
            int col = cbase + ni * 8;
            #pragma unroll
            for (int hf = 0; hf < 2; hf++) {
                int row = rbase + mi * 16 + hf * 8;
                size_t off = (size_t)row * DMODEL + col;
                float v0 = d[mi][ni][hf * 2], v1 = d[mi][ni][hf * 2 + 1];
                if (MODE == 0) {
                    if (wsel == 0) {
                        uint32_t hh, ll;
                        split2h(v0, v1, hh, ll);
                        *(uint32_t*)(g_Qh + off) = hh;
                        *(uint32_t*)(g_Ql + off) = ll;
                    } else {
                        uint32_t p = packhf(v0, v1);
                        *(uint32_t*)(((wsel == 1) ? g_K16 : g_V16) + off) = p;
                    }
                } else {
                    float2 rv = *(const float2*)(resid + off);
                    *(float2*)(outF + off) = make_float2(v0 + rv.x, v1 + rv.y);
                }
            }
        }
}

// ---- attention: fp16 2-term flash, banded ------------------------------------
// smem: Qh @0, Ql @8192; stage s @16384+s*16384: K (8KB), V (8KB)
__device__ __forceinline__ void stage_kv(uint32_t sb, int s, int b, int h,
                                         int krow0, int tid)
{
    const uint32_t base = sb + 16384u + (uint32_t)s * 16384u;
    #pragma unroll
    for (int i = 0; i < 8; i++) {
        int idx = tid + i * 128;
        int mat = idx >> 9, rem = idx & 511;
        int r = rem >> 3, ch = rem & 7;
        const __half* src = (mat ? g_V16 : g_K16)
            + (size_t)(b * SEQL + krow0 + r) * DMODEL + h * HDIM + ch * 8;
        cpa16(base + (uint32_t)mat * 8192u + (uint32_t)r * 128u
                   + (uint32_t)((ch ^ (r & 7)) << 4), src);
    }
}

__global__ __launch_bounds__(128, 2)
void attn_tc()
{
    extern __shared__ char dyn[];
    const uint32_t sb = smem_u32(dyn);
    const int tid = threadIdx.x, wid = tid >> 5, lane = tid & 31;
    const int r8 = lane & 7, g8 = lane >> 3;
    const int qt = blockIdx.x, h = blockIdx.y, b = blockIdx.z;
    const int q0 = qt * 64;

    #pragma unroll
    for (int i = 0; i < 8; i++) {
        int idx = tid + i * 128;
        int mat = idx >> 9, rem = idx & 511;
        int r = rem >> 3, ch = rem & 7;
        const __half* src = (mat ? g_Ql : g_Qh)
            + (size_t)(b * SEQL + q0 + r) * DMODEL + h * HDIM + ch * 8;
        cpa16(sb + (uint32_t)mat * 8192u + (uint32_t)r * 128u
                 + (uint32_t)((ch ^ (r & 7)) << 4), src);
    }
    const int kt_lo = (qt >= 4) ? qt - 4 : 0;
    stage_kv(sb, 0, b, h, kt_lo * 64, tid);
    CP_COMMIT(); CP_WAIT(0);
    __syncthreads();

    uint32_t qh[4][4], ql[4][4];
    #pragma unroll
    for (int k16 = 0; k16 < 4; k16++) {
        int row = wid * 16 + r8 + (g8 & 1) * 8;
        int ch  = k16 * 2 + (g8 >> 1);
        uint32_t off = (uint32_t)row * 128u + (uint32_t)((ch ^ (row & 7)) << 4);
        ldmx4(sb + off, qh[k16]);
        ldmx4(sb + 8192u + off, ql[k16]);
    }

    float o[8][4];
    #pragma unroll
    for (int ni = 0; ni < 8; ni++)
        #pragma unroll
        for (int c = 0; c < 4; c++) o[ni][c] = 0.0f;
    float m_run[2] = {-1e30f, -1e30f}, l_run[2] = {0.0f, 0.0f};

    for (int kt = kt_lo; kt <= qt; kt++) {
        const int s = (kt - kt_lo) & 1;
        if (kt < qt) { stage_kv(sb, s ^ 1, b, h, (kt + 1) * 64, tid); CP_COMMIT(); }
        const uint32_t kb = sb + 16384u + (uint32_t)s * 16384u;

        float sc[8][4];
        #pragma unroll
        for (int ni = 0; ni < 8; ni++)
            #pragma unroll
            for (int c = 0; c < 4; c++) sc[ni][c] = 0.0f;

        #pragma unroll
        for (int k16 = 0; k16 < 4; k16++) {
            uint32_t kh[4][4];
            #pragma unroll
            for (int ng = 0; ng < 4; ng++) {
                int row = ng * 16 + r8 + (g8 >> 1) * 8;
                int ch  = k16 * 2 + (g8 & 1);
                ldmx4(kb + (uint32_t)row * 128u + (uint32_t)((ch ^ (row & 7)) << 4), kh[ng]);
            }
            #pragma unroll
            for (int ng = 0; ng < 4; ng++)
                #pragma unroll
                for (int hf = 0; hf < 2; hf++) {
                    int ni = ng * 2 + hf;
                    mma16816(sc[ni], qh[k16], &kh[ng][hf * 2]);
                    mma16816(sc[ni], ql[k16], &kh[ng][hf * 2]);
                }
        }

        const int k0 = kt * 64;
        if (kt == qt || (qt >= 4 && kt == qt - 4)) {
            const bool diag = (kt == qt);
            const int qr0 = q0 + wid * 16 + (lane >> 2);
            #pragma unroll
            for (int ni = 0; ni < 8; ni++) {
                int kj = k0 + ni * 8 + 2 * (lane & 3);
                #pragma unroll
                for (int c = 0; c < 4; c++) {
                    int kcol = kj + (c & 1), qrow = qr0 + (c >> 1) * 8;
                    bool ok = diag ? (kcol <= qrow) : (kcol >= qrow - (WINDOW - 1));
                    if (!ok) sc[ni][c] = -INFINITY;
                }
            }
        }

        float mt0 = -INFINITY, mt1 = -INFINITY;
        #pragma unroll
        for (int ni = 0; ni < 8; ni++) {
            mt0 = fmaxf(mt0, fmaxf(sc[ni][0], sc[ni][1]));
            mt1 = fmaxf(mt1, fmaxf(sc[ni][2], sc[ni][3]));
        }
        #pragma unroll
        for (int off = 1; off <= 2; off <<= 1) {
            mt0 = fmaxf(mt0, __shfl_xor_sync(0xffffffffu, mt0, off));
            mt1 = fmaxf(mt1, __shfl_xor_sync(0xffffffffu, mt1, off));
        }
        float mn0 = fmaxf(m_run[0], mt0), mn1 = fmaxf(m_run[1], mt1);
        float e0 = __expf(m_run[0] - mn0), e1 = __expf(m_run[1] - mn1);
        float sum0 = 0.0f, sum1 = 0.0f;
        #pragma unroll
        for (int ni = 0; ni < 8; ni++) {
            sc[ni][0] = __expf(sc[ni][0] - mn0); sum0 += sc[ni][0];
            sc[ni][1] = __expf(sc[ni][1] - mn0); sum0 += sc[ni][1];
            sc[ni][2] = __expf(sc[ni][2] - mn1); sum1 += sc[ni][2];
            sc[ni][3] = __expf(sc[ni][3] - mn1); sum1 += sc[ni][3];
        }
        #pragma unroll
        for (int off = 1; off <= 2; off <<= 1) {
            sum0 += __shfl_xor_sync(0xffffffffu, sum0, off);
            sum1 += __shfl_xor_sync(0xffffffffu, sum1, off);
        }
        l_run[0] = l_run[0] * e0 + sum0;
        l_run[1] = l_run[1] * e1 + sum1;
        m_run[0] = mn0; m_run[1] = mn1;
        #pragma unroll
        for (int ni = 0; ni < 8; ni++) {
            o[ni][0] *= e0; o[ni][1] *= e0; o[ni][2] *= e1; o[ni][3] *= e1;
        }

        uint32_t ph[4][4], pl[4][4];
        #pragma unroll
        for (int t = 0; t < 4; t++) {
            split2h(sc[2*t][0],   sc[2*t][1],   ph[t][0], pl[t][0]);
            split2h(sc[2*t][2],   sc[2*t][3],   ph[t][1], pl[t][1]);
            split2h(sc[2*t+1][0], sc[2*t+1][1], ph[t][2], pl[t][2]);
            split2h(sc[2*t+1][2], sc[2*t+1][3], ph[t][3], pl[t][3]);
        }

        const uint32_t vb = kb + 8192u;
        #pragma unroll
        for (int kt16 = 0; kt16 < 4; kt16++) {
            uint32_t vh[4][4];
            #pragma unroll
            for (int ng = 0; ng < 4; ng++) {
                int row = kt16 * 16 + r8 + (g8 & 1) * 8;
                int ch  = ng * 2 + (g8 >> 1);
                ldmx4t(vb + (uint32_t)row * 128u + (uint32_t)((ch ^ (row & 7)) << 4), vh[ng]);
            }
            #pragma unroll
            for (int ng = 0; ng < 4; ng++)
                #pragma unroll
                for (int hf = 0; hf < 2; hf++) {
                    int ni = ng * 2 + hf;
                    mma16816(o[ni], ph[kt16], &vh[ng][hf * 2]);
                    mma16816(o[ni], pl[kt16], &vh[ng][hf * 2]);
                }
        }
        if (kt < qt) { CP_WAIT(0); __syncthreads(); }
    }

    const float i0 = 1.0f / l_run[0], i1 = 1.0f / l_run[1];
    const int row0 = q0 + wid * 16 + (lane >> 2);
    #pragma unroll
    for (int ni = 0; ni < 8; ni++) {
        int col = h * HDIM + ni * 8 + 2 * (lane & 3);
        size_t o0 = (size_t)(b * SEQL + row0) * DMODEL + col;
        size_t o1 = o0 + 8 * DMODEL;
        uint32_t hh, ll;
        split2h(o[ni][0] * i0, o[ni][1] * i0, hh, ll);
        *(uint32_t*)(g_Ch + o0) = hh; *(uint32_t*)(g_Cl + o0) = ll;
        split2h(o[ni][2] * i1, o[ni][3] * i1, hh, ll);
        *(uint32_t*)(g_Ch + o1) = hh; *(uint32_t*)(g_Cl + o1) = ll;
    }
}

// ---- LayerNorm ----------------------------------------------------------------
__global__ __launch_bounds__(256)
void ln_kernel(const float* __restrict__ pre, float* __restrict__ out)
{
    __shared__ float red[16];
    const int row = blockIdx.x, tid = threadIdx.x;
    const float* x = pre + (size_t)row * DMODEL;
    float v0 = x[tid], v1 = x[tid + 256];
    float s = v0 + v1, sq = v0 * v0 + v1 * v1;
    #pragma unroll
    for (int off = 16; off > 0; off >>= 1) {
        s  += __shfl_xor_sync(0xffffffffu, s, off);
        sq += __shfl_xor_sync(0xffffffffu, sq, off);
    }
    if ((tid & 31) == 0) { red[tid >> 5] = s; red[8 + (tid >> 5)] = sq; }
    __syncthreads();
    float st = 0.0f, sqt = 0.0f;
    #pragma unroll
    for (int w = 0; w < 8; w++) { st += red[w]; sqt += red[8 + w]; }
    float mean = st * (1.0f / DMODEL);
    float var  = sqt * (1.0f / DMODEL) - mean * mean;
    float rstd = rsqrtf(var + 1e-5f);
    out[(size_t)row * DMODEL + tid]       = (v0 - mean) * rstd;
    out[(size_t)row * DMODEL + tid + 256] = (v1 - mean) * rstd;
}

// -----------------------------------------------------------------------------------
extern "C" void kernel_launch(void* const* d_in, const int* in_sizes, int n_in,
                              void* d_out, int out_size)
{
    const float* iQ = (const float*)d_in[0];
    const float* iK = (const float*)d_in[1];
    const float* iV = (const float*)d_in[2];
    const float* wQ = (const float*)d_in[3];
    const float* wK = (const float*)d_in[4];
    const float* wV = (const float*)d_in[5];
    const float* wF = (const float*)d_in[6];
    float* out = (float*)d_out;

    float* pPre;
    cudaGetSymbolAddress((void**)&pPre, g_pre);

    prep_w_kernel<<<dim3(16, 16, 4), dim3(32, 8)>>>(wQ, wK, wV, wF);
    prep_x_kernel<<<dim3(MTOT * DMODEL / 4 / 256, 3), 256>>>(iQ, iK, iV);

    const int gemm_smem = 2 * STGB;   // 98304
    cudaFuncSetAttribute((const void*)gemm_tc<0>,
                         cudaFuncAttributeMaxDynamicSharedMemorySize, gemm_smem);
    cudaFuncSetAttribute((const void*)gemm_tc<1>,
                         cudaFuncAttributeMaxDynamicSharedMemorySize, gemm_smem);
    cudaFuncSetAttribute((const void*)attn_tc,
                         cudaFuncAttributeMaxDynamicSharedMemorySize, 49152);

    gemm_tc<0><<<dim3(4, 64, 3), 256, gemm_smem>>>(nullptr, nullptr);
    attn_tc<<<dim3(SEQL / 64, NHEAD, NB), 128, 49152>>>();
    gemm_tc<1><<<dim3(4, 64), 256, gemm_smem>>>(iQ, pPre);
    ln_kernel<<<MTOT, 256>>>(pPre, out);
}

// round 8
// speedup vs baseline: 2.1516x; 1.4885x over previous
#include <cuda_runtime.h>
#include <cuda_fp16.h>
#include <math.h>
#include <stdint.h>

#define NB 4
#define SEQL 2048
#define DMODEL 512
#define NHEAD 8
#define HDIM 64
#define WINDOW 256
#define MTOT (NB*SEQL)
#define XSZ ((size_t)MTOT*DMODEL)
#define WSZ ((size_t)DMODEL*DMODEL)

__device__ __align__(16) float  g_pre[MTOT*DMODEL];
__device__ __align__(16) __half g_W16[4*DMODEL*DMODEL];   // W^T fp16, [w][n][k]
__device__ __align__(16) __half g_X16[3*MTOT*DMODEL];     // inputs fp16
__device__ __align__(16) __half g_Q16[MTOT*DMODEL];
__device__ __align__(16) __half g_K16[MTOT*DMODEL];
__device__ __align__(16) __half g_V16[MTOT*DMODEL];
__device__ __align__(16) __half g_C16[MTOT*DMODEL];       // ctx fp16

__device__ __forceinline__ uint32_t smem_u32(const void* p) {
    uint32_t a;
    asm("{ .reg .u64 t; cvta.to.shared.u64 t, %1; cvt.u32.u64 %0, t; }" : "=r"(a) : "l"(p));
    return a;
}
__device__ __forceinline__ void cpa16(uint32_t dst, const void* src) {
    asm volatile("cp.async.cg.shared.global [%0], [%1], 16;" :: "r"(dst), "l"(src));
}
#define CP_COMMIT() asm volatile("cp.async.commit_group;")
#define CP_WAIT(n)  asm volatile("cp.async.wait_group " #n ";")
__device__ __forceinline__ void ldmx4(uint32_t a, uint32_t* r) {
    asm volatile("ldmatrix.sync.aligned.m8n8.x4.shared.b16 {%0,%1,%2,%3}, [%4];"
                 : "=r"(r[0]), "=r"(r[1]), "=r"(r[2]), "=r"(r[3]) : "r"(a));
}
__device__ __forceinline__ void ldmx4t(uint32_t a, uint32_t* r) {
    asm volatile("ldmatrix.sync.aligned.m8n8.x4.trans.shared.b16 {%0,%1,%2,%3}, [%4];"
                 : "=r"(r[0]), "=r"(r[1]), "=r"(r[2]), "=r"(r[3]) : "r"(a));
}
__device__ __forceinline__ void mma16816(float* d, const uint32_t* a, const uint32_t* b) {
    asm volatile("mma.sync.aligned.m16n8k16.row.col.f32.f16.f16.f32 "
                 "{%0,%1,%2,%3}, {%4,%5,%6,%7}, {%8,%9}, {%0,%1,%2,%3};"
                 : "+f"(d[0]), "+f"(d[1]), "+f"(d[2]), "+f"(d[3])
                 : "r"(a[0]), "r"(a[1]), "r"(a[2]), "r"(a[3]), "r"(b[0]), "r"(b[1]));
}
__device__ __forceinline__ uint32_t packhf(float v0, float v1) {
    __half2 h = __floats2half2_rn(v0, v1);
    return *(uint32_t*)&h;
}

// ---- prep: W^T fp16 (0.125 folded into W_Q) ----------------------------------
__global__ __launch_bounds__(256)
void prep_w_kernel(const float* __restrict__ w0, const float* __restrict__ w1,
                   const float* __restrict__ w2, const float* __restrict__ w3)
{
    __shared__ float s[32][33];
    const int wsel = blockIdx.z;
    const float* W = (wsel == 0) ? w0 : (wsel == 1) ? w1 : (wsel == 2) ? w2 : w3;
    const float scale = (wsel == 0) ? 0.125f : 1.0f;
    const int k0 = blockIdx.x * 32, n0 = blockIdx.y * 32;
    const int tx = threadIdx.x, ty = threadIdx.y;
    #pragma unroll
    for (int i = 0; i < 4; i++)
        s[ty + 8 * i][tx] = W[(size_t)(k0 + ty + 8 * i) * DMODEL + n0 + tx];
    __syncthreads();
    const size_t base = (size_t)wsel * WSZ;
    #pragma unroll
    for (int i = 0; i < 4; i++) {
        int n = n0 + ty + 8 * i, k = k0 + tx;
        g_W16[base + (size_t)n * DMODEL + k] = __float2half_rn(s[tx][ty + 8 * i] * scale);
    }
}

// ---- prep: inputs fp32 -> fp16 --------------------------------------------------
__global__ __launch_bounds__(256)
void prep_x_kernel(const float* __restrict__ x0, const float* __restrict__ x1,
                   const float* __restrict__ x2)
{
    const int sel = blockIdx.y;
    const float* x = (sel == 0) ? x0 : (sel == 1) ? x1 : x2;
    size_t i4 = (size_t)blockIdx.x * 256 + threadIdx.x;
    float4 v = ((const float4*)x)[i4];
    ((uint2*)(g_X16 + (size_t)sel * XSZ))[i4] =
        make_uint2(packhf(v.x, v.y), packhf(v.z, v.w));
}

// ---- GEMM: fp16 single-term, BK=64, 2-stage, 32KB/stage --------------------------
// stage: A @0, B @16384 (each 128 rows x 128B, XOR-swizzled)
#define STGB 32768
__device__ __forceinline__ void stageAB(uint32_t sbase,
    const __half* __restrict__ A, const __half* __restrict__ B,
    int arow, int brow, int k0, int tid)
{
    #pragma unroll
    for (int i = 0; i < 8; i++) {
        int idx = tid + i * 256;
        int mat = idx >> 10, rem = idx & 1023;
        int r = rem >> 3, c = rem & 7;
        const __half* src = mat ? B : A;
        int row = (mat ? brow : arow) + r;
        cpa16(sbase + (uint32_t)(mat << 14) + (uint32_t)r * 128u
                    + (uint32_t)((c ^ (r & 7)) << 4),
              src + (size_t)row * DMODEL + k0 + c * 8);
    }
}

template<int MODE>
__global__ __launch_bounds__(256)
void gemm_tc(const float* __restrict__ resid, float* __restrict__ outF)
{
    extern __shared__ char dyn[];
    const uint32_t sb = smem_u32(dyn);
    const int tid = threadIdx.x, wid = tid >> 5, lane = tid & 31;
    const int wm = wid & 1, wn = wid >> 1;
    const int g8 = lane >> 3, r8 = lane & 7;
    const int bx = blockIdx.x, by = blockIdx.y;
    const int wsel = (MODE == 0) ? (int)blockIdx.z : 3;
    const __half* A = (MODE == 0) ? g_X16 + (size_t)wsel * XSZ : g_C16;
    const __half* B = g_W16 + (size_t)wsel * WSZ;
    const int arow = by * 128, brow = bx * 128;

    float d[4][4][4];
    #pragma unroll
    for (int mi = 0; mi < 4; mi++)
        #pragma unroll
        for (int ni = 0; ni < 4; ni++)
            #pragma unroll
            for (int q = 0; q < 4; q++) d[mi][ni][q] = 0.0f;

    stageAB(sb, A, B, arow, brow, 0, tid);
    CP_COMMIT();

    for (int c = 0; c < 8; c++) {
        if (c < 7) {
            stageAB(sb + (uint32_t)((c + 1) & 1) * STGB, A, B, arow, brow,
                    (c + 1) * 64, tid);
            CP_COMMIT(); CP_WAIT(1);
        } else { CP_WAIT(0); }
        __syncthreads();

        const uint32_t ss = sb + (uint32_t)(c & 1) * STGB;
        #pragma unroll
        for (int k16 = 0; k16 < 4; k16++) {
            uint32_t ah[4][4], bh[8];
            #pragma unroll
            for (int mi = 0; mi < 4; mi++) {
                int row = wm * 64 + mi * 16 + r8 + (g8 & 1) * 8;
                int ch  = k16 * 2 + (g8 >> 1);
                ldmx4(ss + (uint32_t)row * 128u + (uint32_t)((ch ^ (row & 7)) << 4), ah[mi]);
            }
            #pragma unroll
            for (int np = 0; np < 2; np++) {
                int row = wn * 32 + np * 16 + r8 + (g8 >> 1) * 8;
                int ch  = k16 * 2 + (g8 & 1);
                ldmx4(ss + 16384u + (uint32_t)row * 128u
                         + (uint32_t)((ch ^ (row & 7)) << 4), &bh[np * 4]);
            }
            #pragma unroll
            for (int mi = 0; mi < 4; mi++)
                #pragma unroll
                for (int ni = 0; ni < 4; ni++)
                    mma16816(d[mi][ni], ah[mi], &bh[ni * 2]);
        }
        __syncthreads();
    }

    const int rbase = by * 128 + wm * 64 + (lane >> 2);
    const int cbase = bx * 128 + wn * 32 + (lane & 3) * 2;
    #pragma unroll
    for (int mi = 0; mi < 4; mi++)
        #pragma unroll
        for (int ni = 0; ni < 4; ni++) {
            int col = cbase + ni * 8;
            #pragma unroll
            for (int hf = 0; hf < 2; hf++) {
                int row = rbase + mi * 16 + hf * 8;
                size_t off = (size_t)row * DMODEL + col;
                float v0 = d[mi][ni][hf * 2], v1 = d[mi][ni][hf * 2 + 1];
                if (MODE == 0) {
                    __half* dst = (wsel == 0) ? g_Q16 : (wsel == 1) ? g_K16 : g_V16;
                    *(uint32_t*)(dst + off) = packhf(v0, v1);
                } else {
                    float2 rv = *(const float2*)(resid + off);
                    *(float2*)(outF + off) = make_float2(v0 + rv.x, v1 + rv.y);
                }
            }
        }
}

// ---- attention: fp16 single-term flash, banded -----------------------------------
// smem: Q @0 (8KB); stage s @8192+s*16384: K 8KB, V 8KB
__device__ __forceinline__ void stage_kv(uint32_t sb, int s, int b, int h,
                                         int krow0, int tid)
{
    const uint32_t base = sb + 8192u + (uint32_t)s * 16384u;
    #pragma unroll
    for (int i = 0; i < 8; i++) {
        int idx = tid + i * 128;
        int mat = idx >> 9, rem = idx & 511;
        int r = rem >> 3, ch = rem & 7;
        const __half* src = (mat ? g_V16 : g_K16)
            + (size_t)(b * SEQL + krow0 + r) * DMODEL + h * HDIM + ch * 8;
        cpa16(base + (uint32_t)mat * 8192u + (uint32_t)r * 128u
                   + (uint32_t)((ch ^ (r & 7)) << 4), src);
    }
}

__global__ __launch_bounds__(128, 2)
void attn_tc()
{
    extern __shared__ char dyn[];
    const uint32_t sb = smem_u32(dyn);
    const int tid = threadIdx.x, wid = tid >> 5, lane = tid & 31;
    const int r8 = lane & 7, g8 = lane >> 3;
    const int qt = blockIdx.x, h = blockIdx.y, b = blockIdx.z;
    const int q0 = qt * 64;

    #pragma unroll
    for (int i = 0; i < 4; i++) {
        int idx = tid + i * 128;
        int r = idx >> 3, ch = idx & 7;
        const __half* src = g_Q16
            + (size_t)(b * SEQL + q0 + r) * DMODEL + h * HDIM + ch * 8;
        cpa16(sb + (uint32_t)r * 128u + (uint32_t)((ch ^ (r & 7)) << 4), src);
    }
    const int kt_lo = (qt >= 4) ? qt - 4 : 0;
    stage_kv(sb, 0, b, h, kt_lo * 64, tid);
    CP_COMMIT(); CP_WAIT(0);
    __syncthreads();

    uint32_t qh[4][4];
    #pragma unroll
    for (int k16 = 0; k16 < 4; k16++) {
        int row = wid * 16 + r8 + (g8 & 1) * 8;
        int ch  = k16 * 2 + (g8 >> 1);
        ldmx4(sb + (uint32_t)row * 128u + (uint32_t)((ch ^ (row & 7)) << 4), qh[k16]);
    }

    float o[8][4];
    #pragma unroll
    for (int ni = 0; ni < 8; ni++)
        #pragma unroll
        for (int c = 0; c < 4; c++) o[ni][c] = 0.0f;
    float m_run[2] = {-1e30f, -1e30f}, l_run[2] = {0.0f, 0.0f};

    for (int kt = kt_lo; kt <= qt; kt++) {
        const int s = (kt - kt_lo) & 1;
        if (kt < qt) { stage_kv(sb, s ^ 1, b, h, (kt + 1) * 64, tid); CP_COMMIT(); }
        const uint32_t kb = sb + 8192u + (uint32_t)s * 16384u;

        float sc[8][4];
        #pragma unroll
        for (int ni = 0; ni < 8; ni++)
            #pragma unroll
            for (int c = 0; c < 4; c++) sc[ni][c] = 0.0f;

        #pragma unroll
        for (int k16 = 0; k16 < 4; k16++) {
            uint32_t kh[4][4];
            #pragma unroll
            for (int ng = 0; ng < 4; ng++) {
                int row = ng * 16 + r8 + (g8 >> 1) * 8;
                int ch  = k16 * 2 + (g8 & 1);
                ldmx4(kb + (uint32_t)row * 128u + (uint32_t)((ch ^ (row & 7)) << 4), kh[ng]);
            }
            #pragma unroll
            for (int ng = 0; ng < 4; ng++)
                #pragma unroll
                for (int hf = 0; hf < 2; hf++)
                    mma16816(sc[ng * 2 + hf], qh[k16], &kh[ng][hf * 2]);
        }

        const int k0 = kt * 64;
        if (kt == qt || (qt >= 4 && kt == qt - 4)) {
            const bool diag = (kt == qt);
            const int qr0 = q0 + wid * 16 + (lane >> 2);
            #pragma unroll
            for (int ni = 0; ni < 8; ni++) {
                int kj = k0 + ni * 8 + 2 * (lane & 3);
                #pragma unroll
                for (int c = 0; c < 4; c++) {
                    int kcol = kj + (c & 1), qrow = qr0 + (c >> 1) * 8;
                    bool ok = diag ? (kcol <= qrow) : (kcol >= qrow - (WINDOW - 1));
                    if (!ok) sc[ni][c] = -INFINITY;
                }
            }
        }

        float mt0 = -INFINITY, mt1 = -INFINITY;
        #pragma unroll
        for (int ni = 0; ni < 8; ni++) {
            mt0 = fmaxf(mt0, fmaxf(sc[ni][0], sc[ni][1]));
            mt1 = fmaxf(mt1, fmaxf(sc[ni][2], sc[ni][3]));
        }
        #pragma unroll
        for (int off = 1; off <= 2; off <<= 1) {
            mt0 = fmaxf(mt0, __shfl_xor_sync(0xffffffffu, mt0, off));
            mt1 = fmaxf(mt1, __shfl_xor_sync(0xffffffffu, mt1, off));
        }
        float mn0 = fmaxf(m_run[0], mt0), mn1 = fmaxf(m_run[1], mt1);
        float e0 = __expf(m_run[0] - mn0), e1 = __expf(m_run[1] - mn1);
        float sum0 = 0.0f, sum1 = 0.0f;
        #pragma unroll
        for (int ni = 0; ni < 8; ni++) {
            sc[ni][0] = __expf(sc[ni][0] - mn0); sum0 += sc[ni][0];
            sc[ni][1] = __expf(sc[ni][1] - mn0); sum0 += sc[ni][1];
            sc[ni][2] = __expf(sc[ni][2] - mn1); sum1 += sc[ni][2];
            sc[ni][3] = __expf(sc[ni][3] - mn1); sum1 += sc[ni][3];
        }
        #pragma unroll
        for (int off = 1; off <= 2; off <<= 1) {
            sum0 += __shfl_xor_sync(0xffffffffu, sum0, off);
            sum1 += __shfl_xor_sync(0xffffffffu, sum1, off);
        }
        l_run[0] = l_run[0] * e0 + sum0;
        l_run[1] = l_run[1] * e1 + sum1;
        m_run[0] = mn0; m_run[1] = mn1;
        #pragma unroll
        for (int ni = 0; ni < 8; ni++) {
            o[ni][0] *= e0; o[ni][1] *= e0; o[ni][2] *= e1; o[ni][3] *= e1;
        }

        uint32_t ph[4][4];   // P as A-fragments
        #pragma unroll
        for (int t = 0; t < 4; t++) {
            ph[t][0] = packhf(sc[2*t][0],   sc[2*t][1]);
            ph[t][1] = packhf(sc[2*t][2],   sc[2*t][3]);
            ph[t][2] = packhf(sc[2*t+1][0], sc[2*t+1][1]);
            ph[t][3] = packhf(sc[2*t+1][2], sc[2*t+1][3]);
        }

        const uint32_t vb = kb + 8192u;
        #pragma unroll
        for (int kt16 = 0; kt16 < 4; kt16++) {
            uint32_t vh[4][4];
            #pragma unroll
            for (int ng = 0; ng < 4; ng++) {
                int row = kt16 * 16 + r8 + (g8 & 1) * 8;
                int ch  = ng * 2 + (g8 >> 1);
                ldmx4t(vb + (uint32_t)row * 128u + (uint32_t)((ch ^ (row & 7)) << 4), vh[ng]);
            }
            #pragma unroll
            for (int ng = 0; ng < 4; ng++)
                #pragma unroll
                for (int hf = 0; hf < 2; hf++)
                    mma16816(o[ng * 2 + hf], ph[kt16], &vh[ng][hf * 2]);
        }
        if (kt < qt) { CP_WAIT(0); __syncthreads(); }
    }

    const float i0 = 1.0f / l_run[0], i1 = 1.0f / l_run[1];
    const int row0 = q0 + wid * 16 + (lane >> 2);
    #pragma unroll
    for (int ni = 0; ni < 8; ni++) {
        int col = h * HDIM + ni * 8 + 2 * (lane & 3);
        size_t o0 = (size_t)(b * SEQL + row0) * DMODEL + col;
        *(uint32_t*)(g_C16 + o0) = packhf(o[ni][0] * i0, o[ni][1] * i0);
        *(uint32_t*)(g_C16 + o0 + 8 * DMODEL) = packhf(o[ni][2] * i1, o[ni][3] * i1);
    }
}

// ---- LayerNorm ---------------------------------------------------------------------
__global__ __launch_bounds__(256)
void ln_kernel(const float* __restrict__ pre, float* __restrict__ out)
{
    __shared__ float red[16];
    const int row = blockIdx.x, tid = threadIdx.x;
    const float* x = pre + (size_t)row * DMODEL;
    float v0 = x[tid], v1 = x[tid + 256];
    float s = v0 + v1, sq = v0 * v0 + v1 * v1;
    #pragma unroll
    for (int off = 16; off > 0; off >>= 1) {
        s  += __shfl_xor_sync(0xffffffffu, s, off);
        sq += __shfl_xor_sync(0xffffffffu, sq, off);
    }
    if ((tid & 31) == 0) { red[tid >> 5] = s; red[8 + (tid >> 5)] = sq; }
    __syncthreads();
    float st = 0.0f, sqt = 0.0f;
    #pragma unroll
    for (int w = 0; w < 8; w++) { st += red[w]; sqt += red[8 + w]; }
    float mean = st * (1.0f / DMODEL);
    float var  = sqt * (1.0f / DMODEL) - mean * mean;
    float rstd = rsqrtf(var + 1e-5f);
    out[(size_t)row * DMODEL + tid]       = (v0 - mean) * rstd;
    out[(size_t)row * DMODEL + tid + 256] = (v1 - mean) * rstd;
}

// ---------------------------------------------------------------------------------------
extern "C" void kernel_launch(void* const* d_in, const int* in_sizes, int n_in,
                              void* d_out, int out_size)
{
    const float* iQ = (const float*)d_in[0];
    const float* iK = (const float*)d_in[1];
    const float* iV = (const float*)d_in[2];
    const float* wQ = (const float*)d_in[3];
    const float* wK = (const float*)d_in[4];
    const float* wV = (const float*)d_in[5];
    const float* wF = (const float*)d_in[6];
    float* out = (float*)d_out;

    float* pPre;
    cudaGetSymbolAddress((void**)&pPre, g_pre);

    prep_w_kernel<<<dim3(16, 16, 4), dim3(32, 8)>>>(wQ, wK, wV, wF);
    prep_x_kernel<<<dim3(MTOT * DMODEL / 4 / 256, 3), 256>>>(iQ, iK, iV);

    const int gemm_smem = 2 * STGB;   // 65536
    cudaFuncSetAttribute((const void*)gemm_tc<0>,
                         cudaFuncAttributeMaxDynamicSharedMemorySize, gemm_smem);
    cudaFuncSetAttribute((const void*)gemm_tc<1>,
                         cudaFuncAttributeMaxDynamicSharedMemorySize, gemm_smem);
    cudaFuncSetAttribute((const void*)attn_tc,
                         cudaFuncAttributeMaxDynamicSharedMemorySize, 40960);

    gemm_tc<0><<<dim3(4, 64, 3), 256, gemm_smem>>>(nullptr, nullptr);
    attn_tc<<<dim3(SEQL / 64, NHEAD, NB), 128, 40960>>>();
    gemm_tc<1><<<dim3(4, 64), 256, gemm_smem>>>(iQ, pPre);
    ln_kernel<<<MTOT, 256>>>(pPre, out);
}

// round 9
// speedup vs baseline: 2.2266x; 1.0348x over previous
#include <cuda_runtime.h>
#include <cuda_fp16.h>
#include <math.h>
#include <stdint.h>

#define NB 4
#define SEQL 2048
#define DMODEL 512
#define NHEAD 8
#define HDIM 64
#define WINDOW 256
#define MTOT (NB*SEQL)
#define XSZ ((size_t)MTOT*DMODEL)
#define WSZ ((size_t)DMODEL*DMODEL)

__device__ __align__(16) __half g_W16[4*DMODEL*DMODEL];   // W^T fp16, [w][n][k]
__device__ __align__(16) __half g_X16[3*MTOT*DMODEL];     // inputs fp16
__device__ __align__(16) __half g_Q16[MTOT*DMODEL];
__device__ __align__(16) __half g_K16[MTOT*DMODEL];
__device__ __align__(16) __half g_V16[MTOT*DMODEL];
__device__ __align__(16) __half g_C16[MTOT*DMODEL];       // ctx fp16

__device__ __forceinline__ uint32_t smem_u32(const void* p) {
    uint32_t a;
    asm("{ .reg .u64 t; cvta.to.shared.u64 t, %1; cvt.u32.u64 %0, t; }" : "=r"(a) : "l"(p));
    return a;
}
__device__ __forceinline__ void cpa16(uint32_t dst, const void* src) {
    asm volatile("cp.async.cg.shared.global [%0], [%1], 16;" :: "r"(dst), "l"(src));
}
#define CP_COMMIT() asm volatile("cp.async.commit_group;")
#define CP_WAIT(n)  asm volatile("cp.async.wait_group " #n ";")
__device__ __forceinline__ void ldmx4(uint32_t a, uint32_t* r) {
    asm volatile("ldmatrix.sync.aligned.m8n8.x4.shared.b16 {%0,%1,%2,%3}, [%4];"
                 : "=r"(r[0]), "=r"(r[1]), "=r"(r[2]), "=r"(r[3]) : "r"(a));
}
__device__ __forceinline__ void ldmx4t(uint32_t a, uint32_t* r) {
    asm volatile("ldmatrix.sync.aligned.m8n8.x4.trans.shared.b16 {%0,%1,%2,%3}, [%4];"
                 : "=r"(r[0]), "=r"(r[1]), "=r"(r[2]), "=r"(r[3]) : "r"(a));
}
__device__ __forceinline__ void mma16816(float* d, const uint32_t* a, const uint32_t* b) {
    asm volatile("mma.sync.aligned.m16n8k16.row.col.f32.f16.f16.f32 "
                 "{%0,%1,%2,%3}, {%4,%5,%6,%7}, {%8,%9}, {%0,%1,%2,%3};"
                 : "+f"(d[0]), "+f"(d[1]), "+f"(d[2]), "+f"(d[3])
                 : "r"(a[0]), "r"(a[1]), "r"(a[2]), "r"(a[3]), "r"(b[0]), "r"(b[1]));
}
__device__ __forceinline__ uint32_t packhf(float v0, float v1) {
    __half2 h = __floats2half2_rn(v0, v1);
    return *(uint32_t*)&h;
}

// ---- prep: W^T fp16 (0.125 folded into W_Q) ----------------------------------
__global__ __launch_bounds__(256)
void prep_w_kernel(const float* __restrict__ w0, const float* __restrict__ w1,
                   const float* __restrict__ w2, const float* __restrict__ w3)
{
    __shared__ float s[32][33];
    const int wsel = blockIdx.z;
    const float* W = (wsel == 0) ? w0 : (wsel == 1) ? w1 : (wsel == 2) ? w2 : w3;
    const float scale = (wsel == 0) ? 0.125f : 1.0f;
    const int k0 = blockIdx.x * 32, n0 = blockIdx.y * 32;
    const int tx = threadIdx.x, ty = threadIdx.y;
    #pragma unroll
    for (int i = 0; i < 4; i++)
        s[ty + 8 * i][tx] = W[(size_t)(k0 + ty + 8 * i) * DMODEL + n0 + tx];
    __syncthreads();
    const size_t base = (size_t)wsel * WSZ;
    #pragma unroll
    for (int i = 0; i < 4; i++) {
        int n = n0 + ty + 8 * i, k = k0 + tx;
        g_W16[base + (size_t)n * DMODEL + k] = __float2half_rn(s[tx][ty + 8 * i] * scale);
    }
}

// ---- prep: inputs fp32 -> fp16 --------------------------------------------------
__global__ __launch_bounds__(256)
void prep_x_kernel(const float* __restrict__ x0, const float* __restrict__ x1,
                   const float* __restrict__ x2)
{
    const int sel = blockIdx.y;
    const float* x = (sel == 0) ? x0 : (sel == 1) ? x1 : x2;
    size_t i4 = (size_t)blockIdx.x * 256 + threadIdx.x;
    float4 v = ((const float4*)x)[i4];
    ((uint2*)(g_X16 + (size_t)sel * XSZ))[i4] =
        make_uint2(packhf(v.x, v.y), packhf(v.z, v.w));
}

// ---- QKV GEMM: fp16, BK=64, 2-stage, 32KB/stage ----------------------------------
#define STGB 32768
__device__ __forceinline__ void stageAB(uint32_t sbase,
    const __half* __restrict__ A, const __half* __restrict__ B,
    int arow, int brow, int k0, int tid)
{
    #pragma unroll
    for (int i = 0; i < 8; i++) {
        int idx = tid + i * 256;
        int mat = idx >> 10, rem = idx & 1023;
        int r = rem >> 3, c = rem & 7;
        const __half* src = mat ? B : A;
        int row = (mat ? brow : arow) + r;
        cpa16(sbase + (uint32_t)(mat << 14) + (uint32_t)r * 128u
                    + (uint32_t)((c ^ (r & 7)) << 4),
              src + (size_t)row * DMODEL + k0 + c * 8);
    }
}

__global__ __launch_bounds__(256)
void gemm_qkv()
{
    extern __shared__ char dyn[];
    const uint32_t sb = smem_u32(dyn);
    const int tid = threadIdx.x, wid = tid >> 5, lane = tid & 31;
    const int wm = wid & 1, wn = wid >> 1;
    const int g8 = lane >> 3, r8 = lane & 7;
    const int bx = blockIdx.x, by = blockIdx.y;
    const int wsel = blockIdx.z;
    const __half* A = g_X16 + (size_t)wsel * XSZ;
    const __half* B = g_W16 + (size_t)wsel * WSZ;
    const int arow = by * 128, brow = bx * 128;

    float d[4][4][4];
    #pragma unroll
    for (int mi = 0; mi < 4; mi++)
        #pragma unroll
        for (int ni = 0; ni < 4; ni++)
            #pragma unroll
            for (int q = 0; q < 4; q++) d[mi][ni][q] = 0.0f;

    stageAB(sb, A, B, arow, brow, 0, tid);
    CP_COMMIT();

    for (int c = 0; c < 8; c++) {
        if (c < 7) {
            stageAB(sb + (uint32_t)((c + 1) & 1) * STGB, A, B, arow, brow,
                    (c + 1) * 64, tid);
            CP_COMMIT(); CP_WAIT(1);
        } else { CP_WAIT(0); }
        __syncthreads();

        const uint32_t ss = sb + (uint32_t)(c & 1) * STGB;
        #pragma unroll
        for (int k16 = 0; k16 < 4; k16++) {
            uint32_t ah[4][4], bh[8];
            #pragma unroll
            for (int mi = 0; mi < 4; mi++) {
                int row = wm * 64 + mi * 16 + r8 + (g8 & 1) * 8;
                int ch  = k16 * 2 + (g8 >> 1);
                ldmx4(ss + (uint32_t)row * 128u + (uint32_t)((ch ^ (row & 7)) << 4), ah[mi]);
            }
            #pragma unroll
            for (int np = 0; np < 2; np++) {
                int row = wn * 32 + np * 16 + r8 + (g8 >> 1) * 8;
                int ch  = k16 * 2 + (g8 & 1);
                ldmx4(ss + 16384u + (uint32_t)row * 128u
                         + (uint32_t)((ch ^ (row & 7)) << 4), &bh[np * 4]);
            }
            #pragma unroll
            for (int mi = 0; mi < 4; mi++)
                #pragma unroll
                for (int ni = 0; ni < 4; ni++)
                    mma16816(d[mi][ni], ah[mi], &bh[ni * 2]);
        }
        __syncthreads();
    }

    __half* dst = (wsel == 0) ? g_Q16 : (wsel == 1) ? g_K16 : g_V16;
    const int rbase = by * 128 + wm * 64 + (lane >> 2);
    const int cbase = bx * 128 + wn * 32 + (lane & 3) * 2;
    #pragma unroll
    for (int mi = 0; mi < 4; mi++)
        #pragma unroll
        for (int ni = 0; ni < 4; ni++) {
            int col = cbase + ni * 8;
            #pragma unroll
            for (int hf = 0; hf < 2; hf++) {
                int row = rbase + mi * 16 + hf * 8;
                *(uint32_t*)(dst + (size_t)row * DMODEL + col) =
                    packhf(d[mi][ni][hf * 2], d[mi][ni][hf * 2 + 1]);
            }
        }
}

// ---- fused out-proj + residual + LayerNorm -----------------------------------------
// CTA tile: 64 rows x full N=512. 8 warps, warp wn owns n-block wn*64.
// smem: A stages @0/@8192 (8KB each), B stages @16384/@81920 (64KB each),
// red @147456 (2KB), redq @149504 (2KB), stats @151552 (512B).
#define GL_SMEM 152064
__global__ __launch_bounds__(256)
void gemm_ln(const float* __restrict__ resid, float* __restrict__ out)
{
    extern __shared__ char dyn[];
    const uint32_t sb = smem_u32(dyn);
    float* red   = (float*)(dyn + 147456);
    float* redq  = (float*)(dyn + 149504);
    float* stats = (float*)(dyn + 151552);

    const int tid = threadIdx.x, wid = tid >> 5, lane = tid & 31;
    const int g8 = lane >> 3, r8 = lane & 7;
    const int m0 = blockIdx.x * 64;
    const __half* A = g_C16;
    const __half* B = g_W16 + 3 * WSZ;

    // stage helper inline: A 64x64 (8KB), B 512x64 (64KB)
    auto stage = [&](int s, int k0) {
        uint32_t sA = sb + (uint32_t)s * 8192u;
        uint32_t sB = sb + 16384u + (uint32_t)s * 65536u;
        #pragma unroll
        for (int i = 0; i < 2; i++) {
            int idx = tid + i * 256;
            int r = idx >> 3, c = idx & 7;
            cpa16(sA + (uint32_t)r * 128u + (uint32_t)((c ^ (r & 7)) << 4),
                  A + (size_t)(m0 + r) * DMODEL + k0 + c * 8);
        }
        #pragma unroll
        for (int i = 0; i < 16; i++) {
            int idx = tid + i * 256;
            int r = idx >> 3, c = idx & 7;
            cpa16(sB + (uint32_t)r * 128u + (uint32_t)((c ^ (r & 7)) << 4),
                  B + (size_t)r * DMODEL + k0 + c * 8);
        }
    };

    float d[4][8][4];
    #pragma unroll
    for (int mi = 0; mi < 4; mi++)
        #pragma unroll
        for (int ni = 0; ni < 8; ni++)
            #pragma unroll
            for (int q = 0; q < 4; q++) d[mi][ni][q] = 0.0f;

    stage(0, 0);
    CP_COMMIT();

    for (int c = 0; c < 8; c++) {
        if (c < 7) {
            stage((c + 1) & 1, (c + 1) * 64);
            CP_COMMIT(); CP_WAIT(1);
        } else { CP_WAIT(0); }
        __syncthreads();

        const uint32_t sA = sb + (uint32_t)(c & 1) * 8192u;
        const uint32_t sB = sb + 16384u + (uint32_t)(c & 1) * 65536u;
        #pragma unroll
        for (int k16 = 0; k16 < 4; k16++) {
            uint32_t ah[4][4], bh[16];
            #pragma unroll
            for (int mi = 0; mi < 4; mi++) {
                int row = mi * 16 + r8 + (g8 & 1) * 8;
                int ch  = k16 * 2 + (g8 >> 1);
                ldmx4(sA + (uint32_t)row * 128u + (uint32_t)((ch ^ (row & 7)) << 4), ah[mi]);
            }
            #pragma unroll
            for (int np = 0; np < 4; np++) {
                int row = wid * 64 + np * 16 + r8 + (g8 >> 1) * 8;
                int ch  = k16 * 2 + (g8 & 1);
                ldmx4(sB + (uint32_t)row * 128u + (uint32_t)((ch ^ (row & 7)) << 4),
                      &bh[np * 4]);
            }
            #pragma unroll
            for (int mi = 0; mi < 4; mi++)
                #pragma unroll
                for (int ni = 0; ni < 8; ni++)
                    mma16816(d[mi][ni], ah[mi], &bh[(ni >> 1) * 4 + (ni & 1) * 2]);
        }
        __syncthreads();
    }

    // epilogue: residual + per-row partial sums
    const int lrow0 = lane >> 2;
    #pragma unroll
    for (int mi = 0; mi < 4; mi++)
        #pragma unroll
        for (int hf = 0; hf < 2; hf++) {
            int lrow = mi * 16 + hf * 8 + lrow0;
            int grow = m0 + lrow;
            float s = 0.0f, sq = 0.0f;
            #pragma unroll
            for (int ni = 0; ni < 8; ni++) {
                int col = wid * 64 + ni * 8 + (lane & 3) * 2;
                float2 rv = *(const float2*)(resid + (size_t)grow * DMODEL + col);
                float v0 = d[mi][ni][hf * 2]     + rv.x;
                float v1 = d[mi][ni][hf * 2 + 1] + rv.y;
                d[mi][ni][hf * 2]     = v0;
                d[mi][ni][hf * 2 + 1] = v1;
                s  += v0 + v1;
                sq += v0 * v0 + v1 * v1;
            }
            s  += __shfl_xor_sync(0xffffffffu, s, 1);
            s  += __shfl_xor_sync(0xffffffffu, s, 2);
            sq += __shfl_xor_sync(0xffffffffu, sq, 1);
            sq += __shfl_xor_sync(0xffffffffu, sq, 2);
            if ((lane & 3) == 0) {
                red [lrow * 8 + wid] = s;
                redq[lrow * 8 + wid] = sq;
            }
        }
    __syncthreads();

    if (tid < 64) {
        float s = 0.0f, sq = 0.0f;
        #pragma unroll
        for (int w = 0; w < 8; w++) { s += red[tid * 8 + w]; sq += redq[tid * 8 + w]; }
        float mean = s * (1.0f / DMODEL);
        float var  = sq * (1.0f / DMODEL) - mean * mean;
        stats[tid * 2]     = mean;
        stats[tid * 2 + 1] = rsqrtf(var + 1e-5f);
    }
    __syncthreads();

    #pragma unroll
    for (int mi = 0; mi < 4; mi++)
        #pragma unroll
        for (int hf = 0; hf < 2; hf++) {
            int lrow = mi * 16 + hf * 8 + lrow0;
            float mean = stats[lrow * 2], rstd = stats[lrow * 2 + 1];
            int grow = m0 + lrow;
            #pragma unroll
            for (int ni = 0; ni < 8; ni++) {
                int col = wid * 64 + ni * 8 + (lane & 3) * 2;
                float v0 = (d[mi][ni][hf * 2]     - mean) * rstd;
                float v1 = (d[mi][ni][hf * 2 + 1] - mean) * rstd;
                *(float2*)(out + (size_t)grow * DMODEL + col) = make_float2(v0, v1);
            }
        }
}

// ---- attention: fp16 flash, banded (occ bumped to 3 CTAs/SM) ------------------------
__device__ __forceinline__ void stage_kv(uint32_t sb, int s, int b, int h,
                                         int krow0, int tid)
{
    const uint32_t base = sb + 8192u + (uint32_t)s * 16384u;
    #pragma unroll
    for (int i = 0; i < 8; i++) {
        int idx = tid + i * 128;
        int mat = idx >> 9, rem = idx & 511;
        int r = rem >> 3, ch = rem & 7;
        const __half* src = (mat ? g_V16 : g_K16)
            + (size_t)(b * SEQL + krow0 + r) * DMODEL + h * HDIM + ch * 8;
        cpa16(base + (uint32_t)mat * 8192u + (uint32_t)r * 128u
                   + (uint32_t)((ch ^ (r & 7)) << 4), src);
    }
}

__global__ __launch_bounds__(128, 3)
void attn_tc()
{
    extern __shared__ char dyn[];
    const uint32_t sb = smem_u32(dyn);
    const int tid = threadIdx.x, wid = tid >> 5, lane = tid & 31;
    const int r8 = lane & 7, g8 = lane >> 3;
    const int qt = blockIdx.x, h = blockIdx.y, b = blockIdx.z;
    const int q0 = qt * 64;

    #pragma unroll
    for (int i = 0; i < 4; i++) {
        int idx = tid + i * 128;
        int r = idx >> 3, ch = idx & 7;
        const __half* src = g_Q16
            + (size_t)(b * SEQL + q0 + r) * DMODEL + h * HDIM + ch * 8;
        cpa16(sb + (uint32_t)r * 128u + (uint32_t)((ch ^ (r & 7)) << 4), src);
    }
    const int kt_lo = (qt >= 4) ? qt - 4 : 0;
    stage_kv(sb, 0, b, h, kt_lo * 64, tid);
    CP_COMMIT(); CP_WAIT(0);
    __syncthreads();

    uint32_t qh[4][4];
    #pragma unroll
    for (int k16 = 0; k16 < 4; k16++) {
        int row = wid * 16 + r8 + (g8 & 1) * 8;
        int ch  = k16 * 2 + (g8 >> 1);
        ldmx4(sb + (uint32_t)row * 128u + (uint32_t)((ch ^ (row & 7)) << 4), qh[k16]);
    }

    float o[8][4];
    #pragma unroll
    for (int ni = 0; ni < 8; ni++)
        #pragma unroll
        for (int c = 0; c < 4; c++) o[ni][c] = 0.0f;
    float m_run[2] = {-1e30f, -1e30f}, l_run[2] = {0.0f, 0.0f};

    for (int kt = kt_lo; kt <= qt; kt++) {
        const int s = (kt - kt_lo) & 1;
        if (kt < qt) { stage_kv(sb, s ^ 1, b, h, (kt + 1) * 64, tid); CP_COMMIT(); }
        const uint32_t kb = sb + 8192u + (uint32_t)s * 16384u;

        float sc[8][4];
        #pragma unroll
        for (int ni = 0; ni < 8; ni++)
            #pragma unroll
            for (int c = 0; c < 4; c++) sc[ni][c] = 0.0f;

        #pragma unroll
        for (int k16 = 0; k16 < 4; k16++) {
            uint32_t kh[4][4];
            #pragma unroll
            for (int ng = 0; ng < 4; ng++) {
                int row = ng * 16 + r8 + (g8 >> 1) * 8;
                int ch  = k16 * 2 + (g8 & 1);
                ldmx4(kb + (uint32_t)row * 128u + (uint32_t)((ch ^ (row & 7)) << 4), kh[ng]);
            }
            #pragma unroll
            for (int ng = 0; ng < 4; ng++)
                #pragma unroll
                for (int hf = 0; hf < 2; hf++)
                    mma16816(sc[ng * 2 + hf], qh[k16], &kh[ng][hf * 2]);
        }

        const int k0 = kt * 64;
        if (kt == qt || (qt >= 4 && kt == qt - 4)) {
            const bool diag = (kt == qt);
            const int qr0 = q0 + wid * 16 + (lane >> 2);
            #pragma unroll
            for (int ni = 0; ni < 8; ni++) {
                int kj = k0 + ni * 8 + 2 * (lane & 3);
                #pragma unroll
                for (int c = 0; c < 4; c++) {
                    int kcol = kj + (c & 1), qrow = qr0 + (c >> 1) * 8;
                    bool ok = diag ? (kcol <= qrow) : (kcol >= qrow - (WINDOW - 1));
                    if (!ok) sc[ni][c] = -INFINITY;
                }
            }
        }

        float mt0 = -INFINITY, mt1 = -INFINITY;
        #pragma unroll
        for (int ni = 0; ni < 8; ni++) {
            mt0 = fmaxf(mt0, fmaxf(sc[ni][0], sc[ni][1]));
            mt1 = fmaxf(mt1, fmaxf(sc[ni][2], sc[ni][3]));
        }
        #pragma unroll
        for (int off = 1; off <= 2; off <<= 1) {
            mt0 = fmaxf(mt0, __shfl_xor_sync(0xffffffffu, mt0, off));
            mt1 = fmaxf(mt1, __shfl_xor_sync(0xffffffffu, mt1, off));
        }
        float mn0 = fmaxf(m_run[0], mt0), mn1 = fmaxf(m_run[1], mt1);
        float e0 = __expf(m_run[0] - mn0), e1 = __expf(m_run[1] - mn1);
        float sum0 = 0.0f, sum1 = 0.0f;
        #pragma unroll
        for (int ni = 0; ni < 8; ni++) {
            sc[ni][0] = __expf(sc[ni][0] - mn0); sum0 += sc[ni][0];
            sc[ni][1] = __expf(sc[ni][1] - mn0); sum0 += sc[ni][1];
            sc[ni][2] = __expf(sc[ni][2] - mn1); sum1 += sc[ni][2];
            sc[ni][3] = __expf(sc[ni][3] - mn1); sum1 += sc[ni][3];
        }
        #pragma unroll
        for (int off = 1; off <= 2; off <<= 1) {
            sum0 += __shfl_xor_sync(0xffffffffu, sum0, off);
            sum1 += __shfl_xor_sync(0xffffffffu, sum1, off);
        }
        l_run[0] = l_run[0] * e0 + sum0;
        l_run[1] = l_run[1] * e1 + sum1;
        m_run[0] = mn0; m_run[1] = mn1;
        #pragma unroll
        for (int ni = 0; ni < 8; ni++) {
            o[ni][0] *= e0; o[ni][1] *= e0; o[ni][2] *= e1; o[ni][3] *= e1;
        }

        uint32_t ph[4][4];
        #pragma unroll
        for (int t = 0; t < 4; t++) {
            ph[t][0] = packhf(sc[2*t][0],   sc[2*t][1]);
            ph[t][1] = packhf(sc[2*t][2],   sc[2*t][3]);
            ph[t][2] = packhf(sc[2*t+1][0], sc[2*t+1][1]);
            ph[t][3] = packhf(sc[2*t+1][2], sc[2*t+1][3]);
        }

        const uint32_t vb = kb + 8192u;
        #pragma unroll
        for (int kt16 = 0; kt16 < 4; kt16++) {
            uint32_t vh[4][4];
            #pragma unroll
            for (int ng = 0; ng < 4; ng++) {
                int row = kt16 * 16 + r8 + (g8 & 1) * 8;
                int ch  = ng * 2 + (g8 >> 1);
                ldmx4t(vb + (uint32_t)row * 128u + (uint32_t)((ch ^ (row & 7)) << 4), vh[ng]);
            }
            #pragma unroll
            for (int ng = 0; ng < 4; ng++)
                #pragma unroll
                for (int hf = 0; hf < 2; hf++)
                    mma16816(o[ng * 2 + hf], ph[kt16], &vh[ng][hf * 2]);
        }
        if (kt < qt) { CP_WAIT(0); __syncthreads(); }
    }

    const float i0 = 1.0f / l_run[0], i1 = 1.0f / l_run[1];
    const int row0 = q0 + wid * 16 + (lane >> 2);
    #pragma unroll
    for (int ni = 0; ni < 8; ni++) {
        int col = h * HDIM + ni * 8 + 2 * (lane & 3);
        size_t o0 = (size_t)(b * SEQL + row0) * DMODEL + col;
        *(uint32_t*)(g_C16 + o0) = packhf(o[ni][0] * i0, o[ni][1] * i0);
        *(uint32_t*)(g_C16 + o0 + 8 * DMODEL) = packhf(o[ni][2] * i1, o[ni][3] * i1);
    }
}

// ---------------------------------------------------------------------------------------
extern "C" void kernel_launch(void* const* d_in, const int* in_sizes, int n_in,
                              void* d_out, int out_size)
{
    const float* iQ = (const float*)d_in[0];
    const float* iK = (const float*)d_in[1];
    const float* iV = (const float*)d_in[2];
    const float* wQ = (const float*)d_in[3];
    const float* wK = (const float*)d_in[4];
    const float* wV = (const float*)d_in[5];
    const float* wF = (const float*)d_in[6];
    float* out = (float*)d_out;

    prep_w_kernel<<<dim3(16, 16, 4), dim3(32, 8)>>>(wQ, wK, wV, wF);
    prep_x_kernel<<<dim3(MTOT * DMODEL / 4 / 256, 3), 256>>>(iQ, iK, iV);

    const int gemm_smem = 2 * STGB;   // 65536
    cudaFuncSetAttribute((const void*)gemm_qkv,
                         cudaFuncAttributeMaxDynamicSharedMemorySize, gemm_smem);
    cudaFuncSetAttribute((const void*)gemm_ln,
                         cudaFuncAttributeMaxDynamicSharedMemorySize, GL_SMEM);
    cudaFuncSetAttribute((const void*)attn_tc,
                         cudaFuncAttributeMaxDynamicSharedMemorySize, 40960);

    gemm_qkv<<<dim3(4, 64, 3), 256, gemm_smem>>>();
    attn_tc<<<dim3(SEQL / 64, NHEAD, NB), 128, 40960>>>();
    gemm_ln<<<MTOT / 64, 256, GL_SMEM>>>(iQ, out);
}

// round 10
// speedup vs baseline: 2.2993x; 1.0326x over previous
#include <cuda_runtime.h>
#include <cuda_fp16.h>
#include <math.h>
#include <stdint.h>

#define NB 4
#define SEQL 2048
#define DMODEL 512
#define NHEAD 8
#define HDIM 64
#define WINDOW 256
#define MTOT (NB*SEQL)
#define XSZ ((size_t)MTOT*DMODEL)
#define WSZ ((size_t)DMODEL*DMODEL)

__device__ __align__(16) __half g_W16[4*DMODEL*DMODEL];   // W^T fp16, [w][n][k]
__device__ __align__(16) __half g_Q16[MTOT*DMODEL];       // Q has 0.125*log2e folded
__device__ __align__(16) __half g_K16[MTOT*DMODEL];
__device__ __align__(16) __half g_V16[MTOT*DMODEL];
__device__ __align__(16) __half g_C16[MTOT*DMODEL];       // ctx fp16

__device__ __forceinline__ uint32_t smem_u32(const void* p) {
    uint32_t a;
    asm("{ .reg .u64 t; cvta.to.shared.u64 t, %1; cvt.u32.u64 %0, t; }" : "=r"(a) : "l"(p));
    return a;
}
__device__ __forceinline__ void cpa16(uint32_t dst, const void* src) {
    asm volatile("cp.async.cg.shared.global [%0], [%1], 16;" :: "r"(dst), "l"(src));
}
#define CP_COMMIT() asm volatile("cp.async.commit_group;")
#define CP_WAIT(n)  asm volatile("cp.async.wait_group " #n ";")
__device__ __forceinline__ void ldmx4(uint32_t a, uint32_t* r) {
    asm volatile("ldmatrix.sync.aligned.m8n8.x4.shared.b16 {%0,%1,%2,%3}, [%4];"
                 : "=r"(r[0]), "=r"(r[1]), "=r"(r[2]), "=r"(r[3]) : "r"(a));
}
__device__ __forceinline__ void ldmx4t(uint32_t a, uint32_t* r) {
    asm volatile("ldmatrix.sync.aligned.m8n8.x4.trans.shared.b16 {%0,%1,%2,%3}, [%4];"
                 : "=r"(r[0]), "=r"(r[1]), "=r"(r[2]), "=r"(r[3]) : "r"(a));
}
__device__ __forceinline__ void mma16816(float* d, const uint32_t* a, const uint32_t* b) {
    asm volatile("mma.sync.aligned.m16n8k16.row.col.f32.f16.f16.f32 "
                 "{%0,%1,%2,%3}, {%4,%5,%6,%7}, {%8,%9}, {%0,%1,%2,%3};"
                 : "+f"(d[0]), "+f"(d[1]), "+f"(d[2]), "+f"(d[3])
                 : "r"(a[0]), "r"(a[1]), "r"(a[2]), "r"(a[3]), "r"(b[0]), "r"(b[1]));
}
__device__ __forceinline__ uint32_t packhf(float v0, float v1) {
    __half2 h = __floats2half2_rn(v0, v1);
    return *(uint32_t*)&h;
}

// ---- prep: W^T fp16 (0.125*log2e folded into W_Q) ------------------------------
__global__ __launch_bounds__(256)
void prep_w_kernel(const float* __restrict__ w0, const float* __restrict__ w1,
                   const float* __restrict__ w2, const float* __restrict__ w3)
{
    __shared__ float s[32][33];
    const int wsel = blockIdx.z;
    const float* W = (wsel == 0) ? w0 : (wsel == 1) ? w1 : (wsel == 2) ? w2 : w3;
    const float scale = (wsel == 0) ? 0.125f * 1.44269504f : 1.0f;
    const int k0 = blockIdx.x * 32, n0 = blockIdx.y * 32;
    const int tx = threadIdx.x, ty = threadIdx.y;
    #pragma unroll
    for (int i = 0; i < 4; i++)
        s[ty + 8 * i][tx] = W[(size_t)(k0 + ty + 8 * i) * DMODEL + n0 + tx];
    __syncthreads();
    const size_t base = (size_t)wsel * WSZ;
    #pragma unroll
    for (int i = 0; i < 4; i++) {
        int n = n0 + ty + 8 * i, k = k0 + tx;
        g_W16[base + (size_t)n * DMODEL + k] = __float2half_rn(s[tx][ty + 8 * i] * scale);
    }
}

// ---- QKV GEMM: fp16, BK=64, 2-stage; A loaded fp32 directly (prep_x fused) -------
// stage (32KB): A fp16 @0 (16KB), B fp16 @16384 (16KB); XOR-swizzled 128B rows.
#define STGB 32768
__global__ __launch_bounds__(256)
void gemm_qkv(const float* __restrict__ x0, const float* __restrict__ x1,
              const float* __restrict__ x2)
{
    extern __shared__ char dyn[];
    const uint32_t sbu = smem_u32(dyn);
    const int tid = threadIdx.x, wid = tid >> 5, lane = tid & 31;
    const int wm = wid & 1, wn = wid >> 1;
    const int g8 = lane >> 3, r8 = lane & 7;
    const int bx = blockIdx.x, by = blockIdx.y;
    const int wsel = blockIdx.z;
    const float* X = (wsel == 0) ? x0 : (wsel == 1) ? x1 : x2;
    const __half* Bp = g_W16 + (size_t)wsel * WSZ;
    const int arow = by * 128, brow = bx * 128;

    float4 areg[4][2];
    auto ldgA = [&](int k0) {
        #pragma unroll
        for (int i = 0; i < 4; i++) {
            int idx = tid + i * 256;
            int r = idx >> 3, ch = idx & 7;
            const float* src = X + (size_t)(arow + r) * DMODEL + k0 + ch * 8;
            areg[i][0] = *(const float4*)src;
            areg[i][1] = *(const float4*)(src + 4);
        }
    };
    auto stsA = [&](int s) {
        #pragma unroll
        for (int i = 0; i < 4; i++) {
            int idx = tid + i * 256;
            int r = idx >> 3, ch = idx & 7;
            uint4 p;
            p.x = packhf(areg[i][0].x, areg[i][0].y);
            p.y = packhf(areg[i][0].z, areg[i][0].w);
            p.z = packhf(areg[i][1].x, areg[i][1].y);
            p.w = packhf(areg[i][1].z, areg[i][1].w);
            *(uint4*)(dyn + s * STGB + r * 128 + ((ch ^ (r & 7)) << 4)) = p;
        }
    };
    auto cpaB = [&](int s, int k0) {
        uint32_t base = sbu + (uint32_t)s * STGB + 16384u;
        #pragma unroll
        for (int i = 0; i < 4; i++) {
            int idx = tid + i * 256;
            int r = idx >> 3, ch = idx & 7;
            cpa16(base + (uint32_t)r * 128u + (uint32_t)((ch ^ (r & 7)) << 4),
                  Bp + (size_t)(brow + r) * DMODEL + k0 + ch * 8);
        }
    };

    float d[4][4][4];
    #pragma unroll
    for (int mi = 0; mi < 4; mi++)
        #pragma unroll
        for (int ni = 0; ni < 4; ni++)
            #pragma unroll
            for (int q = 0; q < 4; q++) d[mi][ni][q] = 0.0f;

    ldgA(0); stsA(0); cpaB(0, 0); CP_COMMIT();

    for (int c = 0; c < 8; c++) {
        if (c < 7) {
            ldgA((c + 1) * 64);
            cpaB((c + 1) & 1, (c + 1) * 64);
            CP_COMMIT(); CP_WAIT(1);
        } else { CP_WAIT(0); }
        __syncthreads();

        const uint32_t ss = sbu + (uint32_t)(c & 1) * STGB;
        #pragma unroll
        for (int k16 = 0; k16 < 4; k16++) {
            uint32_t ah[4][4], bh[8];
            #pragma unroll
            for (int mi = 0; mi < 4; mi++) {
                int row = wm * 64 + mi * 16 + r8 + (g8 & 1) * 8;
                int ch  = k16 * 2 + (g8 >> 1);
                ldmx4(ss + (uint32_t)row * 128u + (uint32_t)((ch ^ (row & 7)) << 4), ah[mi]);
            }
            #pragma unroll
            for (int np = 0; np < 2; np++) {
                int row = wn * 32 + np * 16 + r8 + (g8 >> 1) * 8;
                int ch  = k16 * 2 + (g8 & 1);
                ldmx4(ss + 16384u + (uint32_t)row * 128u
                         + (uint32_t)((ch ^ (row & 7)) << 4), &bh[np * 4]);
            }
            #pragma unroll
            for (int mi = 0; mi < 4; mi++)
                #pragma unroll
                for (int ni = 0; ni < 4; ni++)
                    mma16816(d[mi][ni], ah[mi], &bh[ni * 2]);
        }
        if (c < 7) stsA((c + 1) & 1);
        __syncthreads();
    }

    __half* dst = (wsel == 0) ? g_Q16 : (wsel == 1) ? g_K16 : g_V16;
    const int rbase = by * 128 + wm * 64 + (lane >> 2);
    const int cbase = bx * 128 + wn * 32 + (lane & 3) * 2;
    #pragma unroll
    for (int mi = 0; mi < 4; mi++)
        #pragma unroll
        for (int ni = 0; ni < 4; ni++) {
            int col = cbase + ni * 8;
            #pragma unroll
            for (int hf = 0; hf < 2; hf++) {
                int row = rbase + mi * 16 + hf * 8;
                *(uint32_t*)(dst + (size_t)row * DMODEL + col) =
                    packhf(d[mi][ni][hf * 2], d[mi][ni][hf * 2 + 1]);
            }
        }
}

// ---- fused out-proj + residual + LayerNorm (unchanged from R9) --------------------
#define GL_SMEM 152064
__global__ __launch_bounds__(256)
void gemm_ln(const float* __restrict__ resid, float* __restrict__ out)
{
    extern __shared__ char dyn[];
    const uint32_t sb = smem_u32(dyn);
    float* red   = (float*)(dyn + 147456);
    float* redq  = (float*)(dyn + 149504);
    float* stats = (float*)(dyn + 151552);

    const int tid = threadIdx.x, wid = tid >> 5, lane = tid & 31;
    const int g8 = lane >> 3, r8 = lane & 7;
    const int m0 = blockIdx.x * 64;
    const __half* A = g_C16;
    const __half* B = g_W16 + 3 * WSZ;

    auto stage = [&](int s, int k0) {
        uint32_t sA = sb + (uint32_t)s * 8192u;
        uint32_t sB = sb + 16384u + (uint32_t)s * 65536u;
        #pragma unroll
        for (int i = 0; i < 2; i++) {
            int idx = tid + i * 256;
            int r = idx >> 3, c = idx & 7;
            cpa16(sA + (uint32_t)r * 128u + (uint32_t)((c ^ (r & 7)) << 4),
                  A + (size_t)(m0 + r) * DMODEL + k0 + c * 8);
        }
        #pragma unroll
        for (int i = 0; i < 16; i++) {
            int idx = tid + i * 256;
            int r = idx >> 3, c = idx & 7;
            cpa16(sB + (uint32_t)r * 128u + (uint32_t)((c ^ (r & 7)) << 4),
                  B + (size_t)r * DMODEL + k0 + c * 8);
        }
    };

    float d[4][8][4];
    #pragma unroll
    for (int mi = 0; mi < 4; mi++)
        #pragma unroll
        for (int ni = 0; ni < 8; ni++)
            #pragma unroll
            for (int q = 0; q < 4; q++) d[mi][ni][q] = 0.0f;

    stage(0, 0);
    CP_COMMIT();

    for (int c = 0; c < 8; c++) {
        if (c < 7) {
            stage((c + 1) & 1, (c + 1) * 64);
            CP_COMMIT(); CP_WAIT(1);
        } else { CP_WAIT(0); }
        __syncthreads();

        const uint32_t sA = sb + (uint32_t)(c & 1) * 8192u;
        const uint32_t sB = sb + 16384u + (uint32_t)(c & 1) * 65536u;
        #pragma unroll
        for (int k16 = 0; k16 < 4; k16++) {
            uint32_t ah[4][4], bh[16];
            #pragma unroll
            for (int mi = 0; mi < 4; mi++) {
                int row = mi * 16 + r8 + (g8 & 1) * 8;
                int ch  = k16 * 2 + (g8 >> 1);
                ldmx4(sA + (uint32_t)row * 128u + (uint32_t)((ch ^ (row & 7)) << 4), ah[mi]);
            }
            #pragma unroll
            for (int np = 0; np < 4; np++) {
                int row = wid * 64 + np * 16 + r8 + (g8 >> 1) * 8;
                int ch  = k16 * 2 + (g8 & 1);
                ldmx4(sB + (uint32_t)row * 128u + (uint32_t)((ch ^ (row & 7)) << 4),
                      &bh[np * 4]);
            }
            #pragma unroll
            for (int mi = 0; mi < 4; mi++)
                #pragma unroll
                for (int ni = 0; ni < 8; ni++)
                    mma16816(d[mi][ni], ah[mi], &bh[(ni >> 1) * 4 + (ni & 1) * 2]);
        }
        __syncthreads();
    }

    const int lrow0 = lane >> 2;
    #pragma unroll
    for (int mi = 0; mi < 4; mi++)
        #pragma unroll
        for (int hf = 0; hf < 2; hf++) {
            int lrow = mi * 16 + hf * 8 + lrow0;
            int grow = m0 + lrow;
            float s = 0.0f, sq = 0.0f;
            #pragma unroll
            for (int ni = 0; ni < 8; ni++) {
                int col = wid * 64 + ni * 8 + (lane & 3) * 2;
                float2 rv = *(const float2*)(resid + (size_t)grow * DMODEL + col);
                float v0 = d[mi][ni][hf * 2]     + rv.x;
                float v1 = d[mi][ni][hf * 2 + 1] + rv.y;
                d[mi][ni][hf * 2]     = v0;
                d[mi][ni][hf * 2 + 1] = v1;
                s  += v0 + v1;
                sq += v0 * v0 + v1 * v1;
            }
            s  += __shfl_xor_sync(0xffffffffu, s, 1);
            s  += __shfl_xor_sync(0xffffffffu, s, 2);
            sq += __shfl_xor_sync(0xffffffffu, sq, 1);
            sq += __shfl_xor_sync(0xffffffffu, sq, 2);
            if ((lane & 3) == 0) {
                red [lrow * 8 + wid] = s;
                redq[lrow * 8 + wid] = sq;
            }
        }
    __syncthreads();

    if (tid < 64) {
        float s = 0.0f, sq = 0.0f;
        #pragma unroll
        for (int w = 0; w < 8; w++) { s += red[tid * 8 + w]; sq += redq[tid * 8 + w]; }
        float mean = s * (1.0f / DMODEL);
        float var  = sq * (1.0f / DMODEL) - mean * mean;
        stats[tid * 2]     = mean;
        stats[tid * 2 + 1] = rsqrtf(var + 1e-5f);
    }
    __syncthreads();

    #pragma unroll
    for (int mi = 0; mi < 4; mi++)
        #pragma unroll
        for (int hf = 0; hf < 2; hf++) {
            int lrow = mi * 16 + hf * 8 + lrow0;
            float mean = stats[lrow * 2], rstd = stats[lrow * 2 + 1];
            int grow = m0 + lrow;
            #pragma unroll
            for (int ni = 0; ni < 8; ni++) {
                int col = wid * 64 + ni * 8 + (lane & 3) * 2;
                float v0 = (d[mi][ni][hf * 2]     - mean) * rstd;
                float v1 = (d[mi][ni][hf * 2 + 1] - mean) * rstd;
                *(float2*)(out + (size_t)grow * DMODEL + col) = make_float2(v0, v1);
            }
        }
}

// ---- attention: fp16 flash, banded, fixed-base softmax (exp2, no running max) ------
__device__ __forceinline__ void stage_kv(uint32_t sb, int s, int b, int h,
                                         int krow0, int tid)
{
    const uint32_t base = sb + 8192u + (uint32_t)s * 16384u;
    #pragma unroll
    for (int i = 0; i < 8; i++) {
        int idx = tid + i * 128;
        int mat = idx >> 9, rem = idx & 511;
        int r = rem >> 3, ch = rem & 7;
        const __half* src = (mat ? g_V16 : g_K16)
            + (size_t)(b * SEQL + krow0 + r) * DMODEL + h * HDIM + ch * 8;
        cpa16(base + (uint32_t)mat * 8192u + (uint32_t)r * 128u
                   + (uint32_t)((ch ^ (r & 7)) << 4), src);
    }
}

__global__ __launch_bounds__(128, 3)
void attn_tc()
{
    extern __shared__ char dyn[];
    const uint32_t sb = smem_u32(dyn);
    const int tid = threadIdx.x, wid = tid >> 5, lane = tid & 31;
    const int r8 = lane & 7, g8 = lane >> 3;
    const int qt = blockIdx.x, h = blockIdx.y, b = blockIdx.z;
    const int q0 = qt * 64;

    #pragma unroll
    for (int i = 0; i < 4; i++) {
        int idx = tid + i * 128;
        int r = idx >> 3, ch = idx & 7;
        const __half* src = g_Q16
            + (size_t)(b * SEQL + q0 + r) * DMODEL + h * HDIM + ch * 8;
        cpa16(sb + (uint32_t)r * 128u + (uint32_t)((ch ^ (r & 7)) << 4), src);
    }
    const int kt_lo = (qt >= 4) ? qt - 4 : 0;
    stage_kv(sb, 0, b, h, kt_lo * 64, tid);
    CP_COMMIT(); CP_WAIT(0);
    __syncthreads();

    uint32_t qh[4][4];
    #pragma unroll
    for (int k16 = 0; k16 < 4; k16++) {
        int row = wid * 16 + r8 + (g8 & 1) * 8;
        int ch  = k16 * 2 + (g8 >> 1);
        ldmx4(sb + (uint32_t)row * 128u + (uint32_t)((ch ^ (row & 7)) << 4), qh[k16]);
    }

    float o[8][4];
    #pragma unroll
    for (int ni = 0; ni < 8; ni++)
        #pragma unroll
        for (int c = 0; c < 4; c++) o[ni][c] = 0.0f;
    float l0 = 0.0f, l1 = 0.0f;

    for (int kt = kt_lo; kt <= qt; kt++) {
        const int s = (kt - kt_lo) & 1;
        if (kt < qt) { stage_kv(sb, s ^ 1, b, h, (kt + 1) * 64, tid); CP_COMMIT(); }
        const uint32_t kb = sb + 8192u + (uint32_t)s * 16384u;

        float sc[8][4];
        #pragma unroll
        for (int ni = 0; ni < 8; ni++)
            #pragma unroll
            for (int c = 0; c < 4; c++) sc[ni][c] = 0.0f;

        #pragma unroll
        for (int k16 = 0; k16 < 4; k16++) {
            uint32_t kh[4][4];
            #pragma unroll
            for (int ng = 0; ng < 4; ng++) {
                int row = ng * 16 + r8 + (g8 >> 1) * 8;
                int ch  = k16 * 2 + (g8 & 1);
                ldmx4(kb + (uint32_t)row * 128u + (uint32_t)((ch ^ (row & 7)) << 4), kh[ng]);
            }
            #pragma unroll
            for (int ng = 0; ng < 4; ng++)
                #pragma unroll
                for (int hf = 0; hf < 2; hf++)
                    mma16816(sc[ng * 2 + hf], qh[k16], &kh[ng][hf * 2]);
        }

        const int k0 = kt * 64;
        if (kt == qt || (qt >= 4 && kt == qt - 4)) {
            const bool diag = (kt == qt);
            const int qr0 = q0 + wid * 16 + (lane >> 2);
            #pragma unroll
            for (int ni = 0; ni < 8; ni++) {
                int kj = k0 + ni * 8 + 2 * (lane & 3);
                #pragma unroll
                for (int c = 0; c < 4; c++) {
                    int kcol = kj + (c & 1), qrow = qr0 + (c >> 1) * 8;
                    bool ok = diag ? (kcol <= qrow) : (kcol >= qrow - (WINDOW - 1));
                    if (!ok) sc[ni][c] = -INFINITY;
                }
            }
        }

        // fixed-base softmax: exp2 directly (scale folded into W_Q), local sums
        #pragma unroll
        for (int ni = 0; ni < 8; ni++) {
            sc[ni][0] = exp2f(sc[ni][0]);
            sc[ni][1] = exp2f(sc[ni][1]);
            sc[ni][2] = exp2f(sc[ni][2]);
            sc[ni][3] = exp2f(sc[ni][3]);
            l0 += sc[ni][0] + sc[ni][1];
            l1 += sc[ni][2] + sc[ni][3];
        }

        uint32_t ph[4][4];
        #pragma unroll
        for (int t = 0; t < 4; t++) {
            ph[t][0] = packhf(sc[2*t][0],   sc[2*t][1]);
            ph[t][1] = packhf(sc[2*t][2],   sc[2*t][3]);
            ph[t][2] = packhf(sc[2*t+1][0], sc[2*t+1][1]);
            ph[t][3] = packhf(sc[2*t+1][2], sc[2*t+1][3]);
        }

        const uint32_t vb = kb + 8192u;
        #pragma unroll
        for (int kt16 = 0; kt16 < 4; kt16++) {
            uint32_t vh[4][4];
            #pragma unroll
            for (int ng = 0; ng < 4; ng++) {
                int row = kt16 * 16 + r8 + (g8 & 1) * 8;
                int ch  = ng * 2 + (g8 >> 1);
                ldmx4t(vb + (uint32_t)row * 128u + (uint32_t)((ch ^ (row & 7)) << 4), vh[ng]);
            }
            #pragma unroll
            for (int ng = 0; ng < 4; ng++)
                #pragma unroll
                for (int hf = 0; hf < 2; hf++)
                    mma16816(o[ng * 2 + hf], ph[kt16], &vh[ng][hf * 2]);
        }
        if (kt < qt) { CP_WAIT(0); __syncthreads(); }
    }

    // single deferred row-sum reduction
    l0 += __shfl_xor_sync(0xffffffffu, l0, 1);
    l0 += __shfl_xor_sync(0xffffffffu, l0, 2);
    l1 += __shfl_xor_sync(0xffffffffu, l1, 1);
    l1 += __shfl_xor_sync(0xffffffffu, l1, 2);

    const float i0 = 1.0f / l0, i1 = 1.0f / l1;
    const int row0 = q0 + wid * 16 + (lane >> 2);
    #pragma unroll
    for (int ni = 0; ni < 8; ni++) {
        int col = h * HDIM + ni * 8 + 2 * (lane & 3);
        size_t o0 = (size_t)(b * SEQL + row0) * DMODEL + col;
        *(uint32_t*)(g_C16 + o0) = packhf(o[ni][0] * i0, o[ni][1] * i0);
        *(uint32_t*)(g_C16 + o0 + 8 * DMODEL) = packhf(o[ni][2] * i1, o[ni][3] * i1);
    }
}

// ---------------------------------------------------------------------------------------
extern "C" void kernel_launch(void* const* d_in, const int* in_sizes, int n_in,
                              void* d_out, int out_size)
{
    const float* iQ = (const float*)d_in[0];
    const float* iK = (const float*)d_in[1];
    const float* iV = (const float*)d_in[2];
    const float* wQ = (const float*)d_in[3];
    const float* wK = (const float*)d_in[4];
    const float* wV = (const float*)d_in[5];
    const float* wF = (const float*)d_in[6];
    float* out = (float*)d_out;

    prep_w_kernel<<<dim3(16, 16, 4), dim3(32, 8)>>>(wQ, wK, wV, wF);

    const int gemm_smem = 2 * STGB;   // 65536
    cudaFuncSetAttribute((const void*)gemm_qkv,
                         cudaFuncAttributeMaxDynamicSharedMemorySize, gemm_smem);
    cudaFuncSetAttribute((const void*)gemm_ln,
                         cudaFuncAttributeMaxDynamicSharedMemorySize, GL_SMEM);
    cudaFuncSetAttribute((const void*)attn_tc,
                         cudaFuncAttributeMaxDynamicSharedMemorySize, 40960);

    gemm_qkv<<<dim3(4, 64, 3), 256, gemm_smem>>>(iQ, iK, iV);
    attn_tc<<<dim3(SEQL / 64, NHEAD, NB), 128, 40960>>>();
    gemm_ln<<<MTOT / 64, 256, GL_SMEM>>>(iQ, out);
}

// round 11
// speedup vs baseline: 2.3196x; 1.0088x over previous
#include <cuda_runtime.h>
#include <cuda_fp16.h>
#include <math.h>
#include <stdint.h>

#define NB 4
#define SEQL 2048
#define DMODEL 512
#define NHEAD 8
#define HDIM 64
#define WINDOW 256
#define MTOT (NB*SEQL)
#define XSZ ((size_t)MTOT*DMODEL)
#define WSZ ((size_t)DMODEL*DMODEL)

__device__ __align__(16) __half g_W16[4*DMODEL*DMODEL];   // W^T fp16, [w][n][k]
__device__ __align__(16) __half g_Q16[MTOT*DMODEL];       // Q has 0.125*log2e folded
__device__ __align__(16) __half g_K16[MTOT*DMODEL];
__device__ __align__(16) __half g_V16[MTOT*DMODEL];
__device__ __align__(16) __half g_C16[MTOT*DMODEL];       // ctx fp16

__device__ __forceinline__ uint32_t smem_u32(const void* p) {
    uint32_t a;
    asm("{ .reg .u64 t; cvta.to.shared.u64 t, %1; cvt.u32.u64 %0, t; }" : "=r"(a) : "l"(p));
    return a;
}
__device__ __forceinline__ void cpa16(uint32_t dst, const void* src) {
    asm volatile("cp.async.cg.shared.global [%0], [%1], 16;" :: "r"(dst), "l"(src));
}
#define CP_COMMIT() asm volatile("cp.async.commit_group;")
#define CP_WAIT(n)  asm volatile("cp.async.wait_group " #n ";")
__device__ __forceinline__ void ldmx4(uint32_t a, uint32_t* r) {
    asm volatile("ldmatrix.sync.aligned.m8n8.x4.shared.b16 {%0,%1,%2,%3}, [%4];"
                 : "=r"(r[0]), "=r"(r[1]), "=r"(r[2]), "=r"(r[3]) : "r"(a));
}
__device__ __forceinline__ void ldmx4t(uint32_t a, uint32_t* r) {
    asm volatile("ldmatrix.sync.aligned.m8n8.x4.trans.shared.b16 {%0,%1,%2,%3}, [%4];"
                 : "=r"(r[0]), "=r"(r[1]), "=r"(r[2]), "=r"(r[3]) : "r"(a));
}
__device__ __forceinline__ void mma16816(float* d, const uint32_t* a, const uint32_t* b) {
    asm volatile("mma.sync.aligned.m16n8k16.row.col.f32.f16.f16.f32 "
                 "{%0,%1,%2,%3}, {%4,%5,%6,%7}, {%8,%9}, {%0,%1,%2,%3};"
                 : "+f"(d[0]), "+f"(d[1]), "+f"(d[2]), "+f"(d[3])
                 : "r"(a[0]), "r"(a[1]), "r"(a[2]), "r"(a[3]), "r"(b[0]), "r"(b[1]));
}
__device__ __forceinline__ uint32_t packhf(float v0, float v1) {
    __half2 h = __floats2half2_rn(v0, v1);
    return *(uint32_t*)&h;
}
__device__ __forceinline__ float ex2(float x) {
    asm("ex2.approx.f32 %0, %0;" : "+f"(x));
    return x;
}

// ---- prep: W^T fp16 (0.125*log2e folded into W_Q) ------------------------------
__global__ __launch_bounds__(256)
void prep_w_kernel(const float* __restrict__ w0, const float* __restrict__ w1,
                   const float* __restrict__ w2, const float* __restrict__ w3)
{
    __shared__ float s[32][33];
    const int wsel = blockIdx.z;
    const float* W = (wsel == 0) ? w0 : (wsel == 1) ? w1 : (wsel == 2) ? w2 : w3;
    const float scale = (wsel == 0) ? 0.125f * 1.44269504f : 1.0f;
    const int k0 = blockIdx.x * 32, n0 = blockIdx.y * 32;
    const int tx = threadIdx.x, ty = threadIdx.y;
    #pragma unroll
    for (int i = 0; i < 4; i++)
        s[ty + 8 * i][tx] = W[(size_t)(k0 + ty + 8 * i) * DMODEL + n0 + tx];
    __syncthreads();
    const size_t base = (size_t)wsel * WSZ;
    #pragma unroll
    for (int i = 0; i < 4; i++) {
        int n = n0 + ty + 8 * i, k = k0 + tx;
        g_W16[base + (size_t)n * DMODEL + k] = __float2half_rn(s[tx][ty + 8 * i] * scale);
    }
}

// ---- QKV GEMM: fp16, BK=64, 2-stage; A loaded fp32 directly ----------------------
#define STGB 32768
__global__ __launch_bounds__(256)
void gemm_qkv(const float* __restrict__ x0, const float* __restrict__ x1,
              const float* __restrict__ x2)
{
    extern __shared__ char dyn[];
    const uint32_t sbu = smem_u32(dyn);
    const int tid = threadIdx.x, wid = tid >> 5, lane = tid & 31;
    const int wm = wid & 1, wn = wid >> 1;
    const int g8 = lane >> 3, r8 = lane & 7;
    const int bx = blockIdx.x, by = blockIdx.y;
    const int wsel = blockIdx.z;
    const float* X = (wsel == 0) ? x0 : (wsel == 1) ? x1 : x2;
    const __half* Bp = g_W16 + (size_t)wsel * WSZ;
    const int arow = by * 128, brow = bx * 128;

    float4 areg[4][2];
    auto ldgA = [&](int k0) {
        #pragma unroll
        for (int i = 0; i < 4; i++) {
            int idx = tid + i * 256;
            int r = idx >> 3, ch = idx & 7;
            const float* src = X + (size_t)(arow + r) * DMODEL + k0 + ch * 8;
            areg[i][0] = *(const float4*)src;
            areg[i][1] = *(const float4*)(src + 4);
        }
    };
    auto stsA = [&](int s) {
        #pragma unroll
        for (int i = 0; i < 4; i++) {
            int idx = tid + i * 256;
            int r = idx >> 3, ch = idx & 7;
            uint4 p;
            p.x = packhf(areg[i][0].x, areg[i][0].y);
            p.y = packhf(areg[i][0].z, areg[i][0].w);
            p.z = packhf(areg[i][1].x, areg[i][1].y);
            p.w = packhf(areg[i][1].z, areg[i][1].w);
            *(uint4*)(dyn + s * STGB + r * 128 + ((ch ^ (r & 7)) << 4)) = p;
        }
    };
    auto cpaB = [&](int s, int k0) {
        uint32_t base = sbu + (uint32_t)s * STGB + 16384u;
        #pragma unroll
        for (int i = 0; i < 4; i++) {
            int idx = tid + i * 256;
            int r = idx >> 3, ch = idx & 7;
            cpa16(base + (uint32_t)r * 128u + (uint32_t)((ch ^ (r & 7)) << 4),
                  Bp + (size_t)(brow + r) * DMODEL + k0 + ch * 8);
        }
    };

    float d[4][4][4];
    #pragma unroll
    for (int mi = 0; mi < 4; mi++)
        #pragma unroll
        for (int ni = 0; ni < 4; ni++)
            #pragma unroll
            for (int q = 0; q < 4; q++) d[mi][ni][q] = 0.0f;

    ldgA(0); stsA(0); cpaB(0, 0); CP_COMMIT();

    for (int c = 0; c < 8; c++) {
        if (c < 7) {
            ldgA((c + 1) * 64);
            cpaB((c + 1) & 1, (c + 1) * 64);
            CP_COMMIT(); CP_WAIT(1);
        } else { CP_WAIT(0); }
        __syncthreads();

        const uint32_t ss = sbu + (uint32_t)(c & 1) * STGB;
        #pragma unroll
        for (int k16 = 0; k16 < 4; k16++) {
            uint32_t ah[4][4], bh[8];
            #pragma unroll
            for (int mi = 0; mi < 4; mi++) {
                int row = wm * 64 + mi * 16 + r8 + (g8 & 1) * 8;
                int ch  = k16 * 2 + (g8 >> 1);
                ldmx4(ss + (uint32_t)row * 128u + (uint32_t)((ch ^ (row & 7)) << 4), ah[mi]);
            }
            #pragma unroll
            for (int np = 0; np < 2; np++) {
                int row = wn * 32 + np * 16 + r8 + (g8 >> 1) * 8;
                int ch  = k16 * 2 + (g8 & 1);
                ldmx4(ss + 16384u + (uint32_t)row * 128u
                         + (uint32_t)((ch ^ (row & 7)) << 4), &bh[np * 4]);
            }
            #pragma unroll
            for (int mi = 0; mi < 4; mi++)
                #pragma unroll
                for (int ni = 0; ni < 4; ni++)
                    mma16816(d[mi][ni], ah[mi], &bh[ni * 2]);
        }
        if (c < 7) stsA((c + 1) & 1);
        __syncthreads();
    }

    __half* dst = (wsel == 0) ? g_Q16 : (wsel == 1) ? g_K16 : g_V16;
    const int rbase = by * 128 + wm * 64 + (lane >> 2);
    const int cbase = bx * 128 + wn * 32 + (lane & 3) * 2;
    #pragma unroll
    for (int mi = 0; mi < 4; mi++)
        #pragma unroll
        for (int ni = 0; ni < 4; ni++) {
            int col = cbase + ni * 8;
            #pragma unroll
            for (int hf = 0; hf < 2; hf++) {
                int row = rbase + mi * 16 + hf * 8;
                *(uint32_t*)(dst + (size_t)row * DMODEL + col) =
                    packhf(d[mi][ni][hf * 2], d[mi][ni][hf * 2 + 1]);
            }
        }
}

// ---- fused out-proj + residual + LayerNorm: 3-stage, prefetch distance 2 ----------
// stage s (73728B): A 64x128B @ s*73728, B 512x128B @ +8192.
// red @221184, redq @223232, stats @225280. total 225792.
#define GLSTG 73728
#define GL_SMEM 225792
__global__ __launch_bounds__(256)
void gemm_ln(const float* __restrict__ resid, float* __restrict__ out)
{
    extern __shared__ char dyn[];
    const uint32_t sb = smem_u32(dyn);
    float* red   = (float*)(dyn + 221184);
    float* redq  = (float*)(dyn + 223232);
    float* stats = (float*)(dyn + 225280);

    const int tid = threadIdx.x, wid = tid >> 5, lane = tid & 31;
    const int g8 = lane >> 3, r8 = lane & 7;
    const int m0 = blockIdx.x * 64;
    const __half* A = g_C16;
    const __half* B = g_W16 + 3 * WSZ;

    auto stage = [&](int s, int k0) {
        uint32_t sA = sb + (uint32_t)s * GLSTG;
        uint32_t sB = sA + 8192u;
        #pragma unroll
        for (int i = 0; i < 2; i++) {
            int idx = tid + i * 256;
            int r = idx >> 3, c = idx & 7;
            cpa16(sA + (uint32_t)r * 128u + (uint32_t)((c ^ (r & 7)) << 4),
                  A + (size_t)(m0 + r) * DMODEL + k0 + c * 8);
        }
        #pragma unroll
        for (int i = 0; i < 16; i++) {
            int idx = tid + i * 256;
            int r = idx >> 3, c = idx & 7;
            cpa16(sB + (uint32_t)r * 128u + (uint32_t)((c ^ (r & 7)) << 4),
                  B + (size_t)r * DMODEL + k0 + c * 8);
        }
    };

    float d[4][8][4];
    #pragma unroll
    for (int mi = 0; mi < 4; mi++)
        #pragma unroll
        for (int ni = 0; ni < 8; ni++)
            #pragma unroll
            for (int q = 0; q < 4; q++) d[mi][ni][q] = 0.0f;

    stage(0, 0);   CP_COMMIT();
    stage(1, 64);  CP_COMMIT();

    for (int c = 0; c < 8; c++) {
        if (c + 2 < 8) {
            stage((c + 2) % 3, (c + 2) * 64);
            CP_COMMIT(); CP_WAIT(2);
        } else if (c + 1 < 8) { CP_WAIT(1); }
        else { CP_WAIT(0); }
        __syncthreads();

        const uint32_t sA = sb + (uint32_t)(c % 3) * GLSTG;
        const uint32_t sB = sA + 8192u;
        #pragma unroll
        for (int k16 = 0; k16 < 4; k16++) {
            uint32_t ah[4][4], bh[16];
            #pragma unroll
            for (int mi = 0; mi < 4; mi++) {
                int row = mi * 16 + r8 + (g8 & 1) * 8;
                int ch  = k16 * 2 + (g8 >> 1);
                ldmx4(sA + (uint32_t)row * 128u + (uint32_t)((ch ^ (row & 7)) << 4), ah[mi]);
            }
            #pragma unroll
            for (int np = 0; np < 4; np++) {
                int row = wid * 64 + np * 16 + r8 + (g8 >> 1) * 8;
                int ch  = k16 * 2 + (g8 & 1);
                ldmx4(sB + (uint32_t)row * 128u + (uint32_t)((ch ^ (row & 7)) << 4),
                      &bh[np * 4]);
            }
            #pragma unroll
            for (int mi = 0; mi < 4; mi++)
                #pragma unroll
                for (int ni = 0; ni < 8; ni++)
                    mma16816(d[mi][ni], ah[mi], &bh[(ni >> 1) * 4 + (ni & 1) * 2]);
        }
        __syncthreads();
    }

    const int lrow0 = lane >> 2;
    #pragma unroll
    for (int mi = 0; mi < 4; mi++)
        #pragma unroll
        for (int hf = 0; hf < 2; hf++) {
            int lrow = mi * 16 + hf * 8 + lrow0;
            int grow = m0 + lrow;
            float s = 0.0f, sq = 0.0f;
            #pragma unroll
            for (int ni = 0; ni < 8; ni++) {
                int col = wid * 64 + ni * 8 + (lane & 3) * 2;
                float2 rv = *(const float2*)(resid + (size_t)grow * DMODEL + col);
                float v0 = d[mi][ni][hf * 2]     + rv.x;
                float v1 = d[mi][ni][hf * 2 + 1] + rv.y;
                d[mi][ni][hf * 2]     = v0;
                d[mi][ni][hf * 2 + 1] = v1;
                s  += v0 + v1;
                sq += v0 * v0 + v1 * v1;
            }
            s  += __shfl_xor_sync(0xffffffffu, s, 1);
            s  += __shfl_xor_sync(0xffffffffu, s, 2);
            sq += __shfl_xor_sync(0xffffffffu, sq, 1);
            sq += __shfl_xor_sync(0xffffffffu, sq, 2);
            if ((lane & 3) == 0) {
                red [lrow * 8 + wid] = s;
                redq[lrow * 8 + wid] = sq;
            }
        }
    __syncthreads();

    if (tid < 64) {
        float s = 0.0f, sq = 0.0f;
        #pragma unroll
        for (int w = 0; w < 8; w++) { s += red[tid * 8 + w]; sq += redq[tid * 8 + w]; }
        float mean = s * (1.0f / DMODEL);
        float var  = sq * (1.0f / DMODEL) - mean * mean;
        stats[tid * 2]     = mean;
        stats[tid * 2 + 1] = rsqrtf(var + 1e-5f);
    }
    __syncthreads();

    #pragma unroll
    for (int mi = 0; mi < 4; mi++)
        #pragma unroll
        for (int hf = 0; hf < 2; hf++) {
            int lrow = mi * 16 + hf * 8 + lrow0;
            float mean = stats[lrow * 2], rstd = stats[lrow * 2 + 1];
            int grow = m0 + lrow;
            #pragma unroll
            for (int ni = 0; ni < 8; ni++) {
                int col = wid * 64 + ni * 8 + (lane & 3) * 2;
                float v0 = (d[mi][ni][hf * 2]     - mean) * rstd;
                float v1 = (d[mi][ni][hf * 2 + 1] - mean) * rstd;
                *(float2*)(out + (size_t)grow * DMODEL + col) = make_float2(v0, v1);
            }
        }
}

// ---- attention: fp16 flash, banded, fixed-base softmax (MUFU.EX2) ------------------
__device__ __forceinline__ void stage_kv(uint32_t sb, int s, int b, int h,
                                         int krow0, int tid)
{
    const uint32_t base = sb + 8192u + (uint32_t)s * 16384u;
    #pragma unroll
    for (int i = 0; i < 8; i++) {
        int idx = tid + i * 128;
        int mat = idx >> 9, rem = idx & 511;
        int r = rem >> 3, ch = rem & 7;
        const __half* src = (mat ? g_V16 : g_K16)
            + (size_t)(b * SEQL + krow0 + r) * DMODEL + h * HDIM + ch * 8;
        cpa16(base + (uint32_t)mat * 8192u + (uint32_t)r * 128u
                   + (uint32_t)((ch ^ (r & 7)) << 4), src);
    }
}

__global__ __launch_bounds__(128, 3)
void attn_tc()
{
    extern __shared__ char dyn[];
    const uint32_t sb = smem_u32(dyn);
    const int tid = threadIdx.x, wid = tid >> 5, lane = tid & 31;
    const int r8 = lane & 7, g8 = lane >> 3;
    const int qt = blockIdx.x, h = blockIdx.y, b = blockIdx.z;
    const int q0 = qt * 64;

    #pragma unroll
    for (int i = 0; i < 4; i++) {
        int idx = tid + i * 128;
        int r = idx >> 3, ch = idx & 7;
        const __half* src = g_Q16
            + (size_t)(b * SEQL + q0 + r) * DMODEL + h * HDIM + ch * 8;
        cpa16(sb + (uint32_t)r * 128u + (uint32_t)((ch ^ (r & 7)) << 4), src);
    }
    const int kt_lo = (qt >= 4) ? qt - 4 : 0;
    stage_kv(sb, 0, b, h, kt_lo * 64, tid);
    CP_COMMIT(); CP_WAIT(0);
    __syncthreads();

    uint32_t qh[4][4];
    #pragma unroll
    for (int k16 = 0; k16 < 4; k16++) {
        int row = wid * 16 + r8 + (g8 & 1) * 8;
        int ch  = k16 * 2 + (g8 >> 1);
        ldmx4(sb + (uint32_t)row * 128u + (uint32_t)((ch ^ (row & 7)) << 4), qh[k16]);
    }

    float o[8][4];
    #pragma unroll
    for (int ni = 0; ni < 8; ni++)
        #pragma unroll
        for (int c = 0; c < 4; c++) o[ni][c] = 0.0f;
    float l0 = 0.0f, l1 = 0.0f;

    for (int kt = kt_lo; kt <= qt; kt++) {
        const int s = (kt - kt_lo) & 1;
        if (kt < qt) { stage_kv(sb, s ^ 1, b, h, (kt + 1) * 64, tid); CP_COMMIT(); }
        const uint32_t kb = sb + 8192u + (uint32_t)s * 16384u;

        float sc[8][4];
        #pragma unroll
        for (int ni = 0; ni < 8; ni++)
            #pragma unroll
            for (int c = 0; c < 4; c++) sc[ni][c] = 0.0f;

        #pragma unroll
        for (int k16 = 0; k16 < 4; k16++) {
            uint32_t kh[4][4];
            #pragma unroll
            for (int ng = 0; ng < 4; ng++) {
                int row = ng * 16 + r8 + (g8 >> 1) * 8;
                int ch  = k16 * 2 + (g8 & 1);
                ldmx4(kb + (uint32_t)row * 128u + (uint32_t)((ch ^ (row & 7)) << 4), kh[ng]);
            }
            #pragma unroll
            for (int ng = 0; ng < 4; ng++)
                #pragma unroll
                for (int hf = 0; hf < 2; hf++)
                    mma16816(sc[ng * 2 + hf], qh[k16], &kh[ng][hf * 2]);
        }

        const int k0 = kt * 64;
        if (kt == qt || (qt >= 4 && kt == qt - 4)) {
            const bool diag = (kt == qt);
            const int qr0 = q0 + wid * 16 + (lane >> 2);
            #pragma unroll
            for (int ni = 0; ni < 8; ni++) {
                int kj = k0 + ni * 8 + 2 * (lane & 3);
                #pragma unroll
                for (int c = 0; c < 4; c++) {
                    int kcol = kj + (c & 1), qrow = qr0 + (c >> 1) * 8;
                    bool ok = diag ? (kcol <= qrow) : (kcol >= qrow - (WINDOW - 1));
                    if (!ok) sc[ni][c] = -INFINITY;
                }
            }
        }

        #pragma unroll
        for (int ni = 0; ni < 8; ni++) {
            sc[ni][0] = ex2(sc[ni][0]);
            sc[ni][1] = ex2(sc[ni][1]);
            sc[ni][2] = ex2(sc[ni][2]);
            sc[ni][3] = ex2(sc[ni][3]);
            l0 += sc[ni][0] + sc[ni][1];
            l1 += sc[ni][2] + sc[ni][3];
        }

        uint32_t ph[4][4];
        #pragma unroll
        for (int t = 0; t < 4; t++) {
            ph[t][0] = packhf(sc[2*t][0],   sc[2*t][1]);
            ph[t][1] = packhf(sc[2*t][2],   sc[2*t][3]);
            ph[t][2] = packhf(sc[2*t+1][0], sc[2*t+1][1]);
            ph[t][3] = packhf(sc[2*t+1][2], sc[2*t+1][3]);
        }

        const uint32_t vb = kb + 8192u;
        #pragma unroll
        for (int kt16 = 0; kt16 < 4; kt16++) {
            uint32_t vh[4][4];
            #pragma unroll
            for (int ng = 0; ng < 4; ng++) {
                int row = kt16 * 16 + r8 + (g8 & 1) * 8;
                int ch  = ng * 2 + (g8 >> 1);
                ldmx4t(vb + (uint32_t)row * 128u + (uint32_t)((ch ^ (row & 7)) << 4), vh[ng]);
            }
            #pragma unroll
            for (int ng = 0; ng < 4; ng++)
                #pragma unroll
                for (int hf = 0; hf < 2; hf++)
                    mma16816(o[ng * 2 + hf], ph[kt16], &vh[ng][hf * 2]);
        }
        if (kt < qt) { CP_WAIT(0); __syncthreads(); }
    }

    l0 += __shfl_xor_sync(0xffffffffu, l0, 1);
    l0 += __shfl_xor_sync(0xffffffffu, l0, 2);
    l1 += __shfl_xor_sync(0xffffffffu, l1, 1);
    l1 += __shfl_xor_sync(0xffffffffu, l1, 2);

    const float i0 = 1.0f / l0, i1 = 1.0f / l1;
    const int row0 = q0 + wid * 16 + (lane >> 2);
    #pragma unroll
    for (int ni = 0; ni < 8; ni++) {
        int col = h * HDIM + ni * 8 + 2 * (lane & 3);
        size_t o0 = (size_t)(b * SEQL + row0) * DMODEL + col;
        *(uint32_t*)(g_C16 + o0) = packhf(o[ni][0] * i0, o[ni][1] * i0);
        *(uint32_t*)(g_C16 + o0 + 8 * DMODEL) = packhf(o[ni][2] * i1, o[ni][3] * i1);
    }
}

// ---------------------------------------------------------------------------------------
extern "C" void kernel_launch(void* const* d_in, const int* in_sizes, int n_in,
                              void* d_out, int out_size)
{
    const float* iQ = (const float*)d_in[0];
    const float* iK = (const float*)d_in[1];
    const float* iV = (const float*)d_in[2];
    const float* wQ = (const float*)d_in[3];
    const float* wK = (const float*)d_in[4];
    const float* wV = (const float*)d_in[5];
    const float* wF = (const float*)d_in[6];
    float* out = (float*)d_out;

    prep_w_kernel<<<dim3(16, 16, 4), dim3(32, 8)>>>(wQ, wK, wV, wF);

    const int gemm_smem = 2 * STGB;   // 65536
    cudaFuncSetAttribute((const void*)gemm_qkv,
                         cudaFuncAttributeMaxDynamicSharedMemorySize, gemm_smem);
    cudaFuncSetAttribute((const void*)gemm_ln,
                         cudaFuncAttributeMaxDynamicSharedMemorySize, GL_SMEM);
    cudaFuncSetAttribute((const void*)attn_tc,
                         cudaFuncAttributeMaxDynamicSharedMemorySize, 40960);

    gemm_qkv<<<dim3(4, 64, 3), 256, gemm_smem>>>(iQ, iK, iV);
    attn_tc<<<dim3(SEQL / 64, NHEAD, NB), 128, 40960>>>();
    gemm_ln<<<MTOT / 64, 256, GL_SMEM>>>(iQ, out);
}